// round 1
// baseline (speedup 1.0000x reference)
#include <cuda_runtime.h>
#include <cuda_bf16.h>
#include <math.h>

#define S_LEN 4096
#define HIDDEN 2048
#define NH 16
#define NKV 4
#define HD 128

// Scratch (device globals: allowed; runtime alloc is not)
__device__ float g_Qraw[S_LEN * HIDDEN];
__device__ float g_Kraw[S_LEN * NKV * HD];
__device__ float g_Vraw[S_LEN * NKV * HD];
__device__ float g_Qn[S_LEN * HIDDEN];      // [h][s][d]
__device__ float g_Kn[S_LEN * NKV * HD];    // [kv][s][d]
__device__ float g_Vn[S_LEN * NKV * HD];    // [kv][s][d]
__device__ float g_AO[S_LEN * HIDDEN];      // [s][h*128+d]

// ---------------------------------------------------------------------------
// C[M,N] = A[M,K] @ B[N,K]^T   (both row-major, K contiguous)
// 128x128x16 tiles, 256 threads, 8x8 microtile.
// ---------------------------------------------------------------------------
__global__ void __launch_bounds__(256) gemm_nt_kernel(
    const float* __restrict__ A, const float* __restrict__ B,
    float* __restrict__ C, int M, int N, int K)
{
    __shared__ float As[16][132];   // [k][row], padded for banks + 16B align
    __shared__ float Bs[16][132];

    const int tid = threadIdx.x;
    const int tx = tid & 15, ty = tid >> 4;
    const float* Ab = A + (size_t)blockIdx.y * 128 * K;
    const float* Bb = B + (size_t)blockIdx.x * 128 * K;

    float acc[8][8];
#pragma unroll
    for (int i = 0; i < 8; i++)
#pragma unroll
        for (int j = 0; j < 8; j++) acc[i][j] = 0.f;

    for (int k0 = 0; k0 < K; k0 += 16) {
#pragma unroll
        for (int i = 0; i < 2; i++) {
            int f = tid + i * 256;          // 0..511 float4 slots
            int row = f >> 2;               // 0..127
            int kc = (f & 3) << 2;          // 0,4,8,12
            float4 a4 = *(const float4*)(Ab + (size_t)row * K + k0 + kc);
            As[kc + 0][row] = a4.x; As[kc + 1][row] = a4.y;
            As[kc + 2][row] = a4.z; As[kc + 3][row] = a4.w;
            float4 b4 = *(const float4*)(Bb + (size_t)row * K + k0 + kc);
            Bs[kc + 0][row] = b4.x; Bs[kc + 1][row] = b4.y;
            Bs[kc + 2][row] = b4.z; Bs[kc + 3][row] = b4.w;
        }
        __syncthreads();
#pragma unroll
        for (int k = 0; k < 16; k++) {
            float4 a0 = *(const float4*)(&As[k][ty * 8]);
            float4 a1 = *(const float4*)(&As[k][ty * 8 + 4]);
            float4 b0 = *(const float4*)(&Bs[k][tx * 8]);
            float4 b1 = *(const float4*)(&Bs[k][tx * 8 + 4]);
            float ra[8] = {a0.x, a0.y, a0.z, a0.w, a1.x, a1.y, a1.z, a1.w};
            float rb[8] = {b0.x, b0.y, b0.z, b0.w, b1.x, b1.y, b1.z, b1.w};
#pragma unroll
            for (int i = 0; i < 8; i++)
#pragma unroll
                for (int j = 0; j < 8; j++)
                    acc[i][j] += ra[i] * rb[j];
        }
        __syncthreads();
    }

#pragma unroll
    for (int i = 0; i < 8; i++) {
        float* Cr = C + (size_t)(blockIdx.y * 128 + ty * 8 + i) * N
                      + blockIdx.x * 128 + tx * 8;
        *(float4*)(Cr)     = make_float4(acc[i][0], acc[i][1], acc[i][2], acc[i][3]);
        *(float4*)(Cr + 4) = make_float4(acc[i][4], acc[i][5], acc[i][6], acc[i][7]);
    }
}

// ---------------------------------------------------------------------------
// Per-(s,head) RMSNorm (+ optional weight) (+ optional RoPE).
// One warp per task; 4 elements per lane: d = lane, lane+32, lane+64, lane+96.
// Input:  in[s][nheads*128 + h*128 + d]   (GEMM output layout)
// Output: out[h][s][d]                    (head-major, for attention)
// ---------------------------------------------------------------------------
__global__ void __launch_bounds__(128) norm_rope_kernel(
    const float* __restrict__ in, float* __restrict__ out,
    const float* __restrict__ w,
    const float* __restrict__ cosT, const float* __restrict__ sinT,
    int nheads, int use_rope)
{
    int task = blockIdx.x * 4 + (threadIdx.x >> 5);
    int lane = threadIdx.x & 31;
    if (task >= S_LEN * nheads) return;
    int s = task / nheads, h = task - s * nheads;

    const float* x = in + (size_t)s * (nheads * HD) + h * HD;
    float v0 = x[lane], v1 = x[lane + 32], v2 = x[lane + 64], v3 = x[lane + 96];
    float ss = v0 * v0 + v1 * v1 + v2 * v2 + v3 * v3;
#pragma unroll
    for (int o = 16; o > 0; o >>= 1) ss += __shfl_xor_sync(0xFFFFFFFFu, ss, o);
    float inv = rsqrtf(ss * (1.f / HD) + 1e-6f);
    float n0 = v0 * inv, n1 = v1 * inv, n2 = v2 * inv, n3 = v3 * inv;
    if (w) {
        n0 *= w[lane]; n1 *= w[lane + 32]; n2 *= w[lane + 64]; n3 *= w[lane + 96];
    }
    float o0 = n0, o1 = n1, o2 = n2, o3 = n3;
    if (use_rope) {
        const float* c  = cosT + (size_t)s * HD;
        const float* sn = sinT + (size_t)s * HD;
        // rotate_half on normalized values: rot = [-n[64:], n[:64]]
        o0 = n0 * c[lane]      - n2 * sn[lane];
        o1 = n1 * c[lane + 32] - n3 * sn[lane + 32];
        o2 = n2 * c[lane + 64] + n0 * sn[lane + 64];
        o3 = n3 * c[lane + 96] + n1 * sn[lane + 96];
    }
    float* y = out + ((size_t)h * S_LEN + s) * HD;
    y[lane] = o0; y[lane + 32] = o1; y[lane + 64] = o2; y[lane + 96] = o3;
}

// ---------------------------------------------------------------------------
// Causal flash attention, scale = 1.0, GQA (head h uses kv head h/4).
// Block = (row_block rb of 64 q-rows, head h). 256 threads.
// smem: Qt[128][68] (transposed), Kt[128][68], Vs[64][128], Ss[64][65], m/l/a[64]
// ---------------------------------------------------------------------------
#define QT_STRIDE 68
#define SS_STRIDE 65
#define ATTN_SMEM_FLOATS (128 * QT_STRIDE * 2 + 64 * 128 + 64 * SS_STRIDE + 3 * 64)

__global__ void __launch_bounds__(256) attn_kernel(
    const float* __restrict__ Q, const float* __restrict__ K,
    const float* __restrict__ V, float* __restrict__ O)
{
    extern __shared__ float sm[];
    float* Qt   = sm;                          // [128][68]
    float* Kt   = Qt + 128 * QT_STRIDE;        // [128][68]
    float* Vs   = Kt + 128 * QT_STRIDE;        // [64][128]
    float* Ss   = Vs + 64 * 128;               // [64][65]
    float* mrow = Ss + 64 * SS_STRIDE;
    float* lrow = mrow + 64;
    float* arow = lrow + 64;

    const int rb = blockIdx.x;
    const int h  = blockIdx.y;
    const int kvh = h >> 2;
    const int tid = threadIdx.x;
    const int tx = tid & 15, ty = tid >> 4;

    const float* Qg = Q + ((size_t)h * S_LEN + rb * 64) * HD;
    const float* Kg = K + (size_t)kvh * S_LEN * HD;
    const float* Vg = V + (size_t)kvh * S_LEN * HD;

    // load Q tile transposed: Qt[d][row]
    for (int idx = tid; idx < 64 * 32; idx += 256) {
        int row = idx >> 5;
        int c4 = (idx & 31) << 2;
        float4 q4 = *(const float4*)(Qg + (size_t)row * HD + c4);
        Qt[(c4 + 0) * QT_STRIDE + row] = q4.x;
        Qt[(c4 + 1) * QT_STRIDE + row] = q4.y;
        Qt[(c4 + 2) * QT_STRIDE + row] = q4.z;
        Qt[(c4 + 3) * QT_STRIDE + row] = q4.w;
    }
    if (tid < 64) { mrow[tid] = -INFINITY; lrow[tid] = 0.f; }

    float acc[4][8];
#pragma unroll
    for (int i = 0; i < 4; i++)
#pragma unroll
        for (int j = 0; j < 8; j++) acc[i][j] = 0.f;

    for (int kb = 0; kb <= rb; kb++) {
        __syncthreads();   // prev PV done (and Q/m/l init on first iter)
        const float* Kgb = Kg + (size_t)kb * 64 * HD;
        const float* Vgb = Vg + (size_t)kb * 64 * HD;
        for (int idx = tid; idx < 64 * 32; idx += 256) {
            int row = idx >> 5;
            int c4 = (idx & 31) << 2;
            float4 k4 = *(const float4*)(Kgb + (size_t)row * HD + c4);
            Kt[(c4 + 0) * QT_STRIDE + row] = k4.x;
            Kt[(c4 + 1) * QT_STRIDE + row] = k4.y;
            Kt[(c4 + 2) * QT_STRIDE + row] = k4.z;
            Kt[(c4 + 3) * QT_STRIDE + row] = k4.w;
            *(float4*)(Vs + row * HD + c4) = *(const float4*)(Vgb + (size_t)row * HD + c4);
        }
        __syncthreads();

        // S = Q K^T : each thread 4x4
        float sacc[4][4];
#pragma unroll
        for (int i = 0; i < 4; i++)
#pragma unroll
            for (int j = 0; j < 4; j++) sacc[i][j] = 0.f;

        for (int k = 0; k < 128; k++) {
            float4 qa = *(const float4*)(Qt + k * QT_STRIDE + ty * 4);
            float4 kv = *(const float4*)(Kt + k * QT_STRIDE + tx * 4);
            float ra[4] = {qa.x, qa.y, qa.z, qa.w};
            float rbv[4] = {kv.x, kv.y, kv.z, kv.w};
#pragma unroll
            for (int i = 0; i < 4; i++)
#pragma unroll
                for (int j = 0; j < 4; j++)
                    sacc[i][j] += ra[i] * rbv[j];
        }
        bool diag = (kb == rb);
#pragma unroll
        for (int i = 0; i < 4; i++)
#pragma unroll
            for (int j = 0; j < 4; j++) {
                float sv = sacc[i][j];
                if (diag && (tx * 4 + j) > (ty * 4 + i)) sv = -INFINITY;
                Ss[(ty * 4 + i) * SS_STRIDE + tx * 4 + j] = sv;
            }
        __syncthreads();

        // online softmax, one thread per row
        if (tid < 64) {
            int r = tid;
            float mloc = -INFINITY;
            for (int c = 0; c < 64; c++) mloc = fmaxf(mloc, Ss[r * SS_STRIDE + c]);
            float mold = mrow[r];
            float mnew = fmaxf(mold, mloc);
            float al = __expf(mold - mnew);   // 0 on first block
            float lsum = 0.f;
            for (int c = 0; c < 64; c++) {
                float p = __expf(Ss[r * SS_STRIDE + c] - mnew);
                Ss[r * SS_STRIDE + c] = p;
                lsum += p;
            }
            lrow[r] = lrow[r] * al + lsum;
            mrow[r] = mnew;
            arow[r] = al;
        }
        __syncthreads();

        // rescale + O += P @ V : each thread 4 rows x 8 cols
        float al[4];
#pragma unroll
        for (int i = 0; i < 4; i++) al[i] = arow[ty * 4 + i];
#pragma unroll
        for (int i = 0; i < 4; i++)
#pragma unroll
            for (int j = 0; j < 8; j++) acc[i][j] *= al[i];

        for (int jv = 0; jv < 64; jv++) {
            float4 v0 = *(const float4*)(Vs + jv * HD + tx * 8);
            float4 v1 = *(const float4*)(Vs + jv * HD + tx * 8 + 4);
            float vv[8] = {v0.x, v0.y, v0.z, v0.w, v1.x, v1.y, v1.z, v1.w};
#pragma unroll
            for (int i = 0; i < 4; i++) {
                float p = Ss[(ty * 4 + i) * SS_STRIDE + jv];
#pragma unroll
                for (int j = 0; j < 8; j++) acc[i][j] += p * vv[j];
            }
        }
    }

    // normalize + write: O[s][h*128 + c]
    float linv[4];
#pragma unroll
    for (int i = 0; i < 4; i++) linv[i] = 1.f / lrow[ty * 4 + i];
#pragma unroll
    for (int i = 0; i < 4; i++) {
        int s = rb * 64 + ty * 4 + i;
        float* og = O + (size_t)s * HIDDEN + h * HD + tx * 8;
        *(float4*)(og)     = make_float4(acc[i][0] * linv[i], acc[i][1] * linv[i],
                                         acc[i][2] * linv[i], acc[i][3] * linv[i]);
        *(float4*)(og + 4) = make_float4(acc[i][4] * linv[i], acc[i][5] * linv[i],
                                         acc[i][6] * linv[i], acc[i][7] * linv[i]);
    }
}

// ---------------------------------------------------------------------------
extern "C" void kernel_launch(void* const* d_in, const int* in_sizes, int n_in,
                              void* d_out, int out_size)
{
    const float* hs   = (const float*)d_in[0];
    const float* cosT = (const float*)d_in[1];
    const float* sinT = (const float*)d_in[2];
    // d_in[3] = attention_mask: pure causal, implemented directly (not read)
    const float* Wq = (const float*)d_in[4];
    const float* Wk = (const float*)d_in[5];
    const float* Wv = (const float*)d_in[6];
    const float* Wo = (const float*)d_in[7];
    const float* qw = (const float*)d_in[8];
    const float* kw = (const float*)d_in[9];
    float* out = (float*)d_out;

    float *qraw, *kraw, *vraw, *qn, *kn, *vn, *ao;
    cudaGetSymbolAddress((void**)&qraw, g_Qraw);
    cudaGetSymbolAddress((void**)&kraw, g_Kraw);
    cudaGetSymbolAddress((void**)&vraw, g_Vraw);
    cudaGetSymbolAddress((void**)&qn, g_Qn);
    cudaGetSymbolAddress((void**)&kn, g_Kn);
    cudaGetSymbolAddress((void**)&vn, g_Vn);
    cudaGetSymbolAddress((void**)&ao, g_AO);

    // QKV projections
    gemm_nt_kernel<<<dim3(HIDDEN / 128, S_LEN / 128), 256>>>(hs, Wq, qraw, S_LEN, HIDDEN, HIDDEN);
    gemm_nt_kernel<<<dim3(NKV * HD / 128, S_LEN / 128), 256>>>(hs, Wk, kraw, S_LEN, NKV * HD, HIDDEN);
    gemm_nt_kernel<<<dim3(NKV * HD / 128, S_LEN / 128), 256>>>(hs, Wv, vraw, S_LEN, NKV * HD, HIDDEN);

    // RMSNorm (+RoPE) -> head-major layouts
    norm_rope_kernel<<<(S_LEN * NH + 3) / 4, 128>>>(qraw, qn, qw, cosT, sinT, NH, 1);
    norm_rope_kernel<<<(S_LEN * NKV + 3) / 4, 128>>>(kraw, kn, kw, cosT, sinT, NKV, 1);
    norm_rope_kernel<<<(S_LEN * NKV + 3) / 4, 128>>>(vraw, vn, nullptr, cosT, sinT, NKV, 0);

    // Causal GQA flash attention
    size_t attn_smem = ATTN_SMEM_FLOATS * sizeof(float);
    cudaFuncSetAttribute(attn_kernel, cudaFuncAttributeMaxDynamicSharedMemorySize, (int)attn_smem);
    attn_kernel<<<dim3(S_LEN / 64, NH), 256, attn_smem>>>(qn, kn, vn, ao);

    // Output projection
    gemm_nt_kernel<<<dim3(HIDDEN / 128, S_LEN / 128), 256>>>(ao, Wo, out, S_LEN, HIDDEN, HIDDEN);
}

// round 2
// speedup vs baseline: 1.7373x; 1.7373x over previous
#include <cuda_runtime.h>
#include <cuda_bf16.h>
#include <math.h>
#include <stdint.h>

#define S_LEN 4096
#define HIDDEN 2048
#define NH 16
#define NKV 4
#define HD 128

// Scratch (device globals: allowed; runtime alloc is not)
__device__ float g_Qraw[S_LEN * HIDDEN];
__device__ float g_Kraw[S_LEN * NKV * HD];
__device__ float g_Vraw[S_LEN * NKV * HD];
__device__ float g_Qn[S_LEN * HIDDEN];      // [h][s][d]
__device__ float g_Kn[S_LEN * NKV * HD];    // [kv][s][d]
__device__ float g_Vn[S_LEN * NKV * HD];    // [kv][s][d]
__device__ float g_AO[S_LEN * HIDDEN];      // [s][h*128+d]

// ---------------------------------------------------------------------------
// tf32 helpers
// ---------------------------------------------------------------------------
__device__ __forceinline__ uint32_t f2tf(float x) {
    uint32_t r;
    asm("cvt.rna.tf32.f32 %0, %1;" : "=r"(r) : "f"(x));
    return r;
}
__device__ __forceinline__ void split_tf32(float x, float& h, float& l) {
    uint32_t hb;
    asm("cvt.rna.tf32.f32 %0, %1;" : "=r"(hb) : "f"(x));
    h = __uint_as_float(hb);
    float r = x - h;
    uint32_t lb;
    asm("cvt.rna.tf32.f32 %0, %1;" : "=r"(lb) : "f"(r));
    l = __uint_as_float(lb);
}
#define U(x) __float_as_uint(x)

// D += A(16x8) * B(8x8), tf32 inputs, f32 accum.
// A frag: a0=(g,t4) a1=(g+8,t4) a2=(g,t4+4) a3=(g+8,t4+4); g=lane>>2, t4=lane&3
// B frag: b0=(k=t4, n=g) b1=(k=t4+4, n=g)
// C frag: c0=(g,2t4) c1=(g,2t4+1) c2=(g+8,2t4) c3=(g+8,2t4+1)
__device__ __forceinline__ void mma8(float* c, const uint32_t* a, const uint32_t* b) {
    asm volatile(
        "mma.sync.aligned.m16n8k8.row.col.f32.tf32.tf32.f32 "
        "{%0,%1,%2,%3},{%4,%5,%6,%7},{%8,%9},{%0,%1,%2,%3};\n"
        : "+f"(c[0]), "+f"(c[1]), "+f"(c[2]), "+f"(c[3])
        : "r"(a[0]), "r"(a[1]), "r"(a[2]), "r"(a[3]), "r"(b[0]), "r"(b[1]));
}

// ---------------------------------------------------------------------------
// C[M,N] = A[M,K] @ B[N,K]^T via 3xTF32 mma. 128x128 block, k-chunk 32,
// 256 threads = 8 warps, warp tile 32(m) x 64(n).
// ---------------------------------------------------------------------------
#define GBK 32
#define GLD 36
#define GEMM_SMEM_BYTES (4 * 128 * GLD * 4)

__global__ void __launch_bounds__(256) gemm_tf32x3_kernel(
    const float* __restrict__ A, const float* __restrict__ B,
    float* __restrict__ C, int M, int N, int K)
{
    extern __shared__ float sm[];
    float* Ah = sm;
    float* Al = Ah + 128 * GLD;
    float* Bh = Al + 128 * GLD;
    float* Bl = Bh + 128 * GLD;

    const int tid = threadIdx.x, w = tid >> 5, lane = tid & 31;
    const int g = lane >> 2, t4 = lane & 3;
    const int wm = w >> 1, wn = w & 1;   // warp tile origin: (32*wm, 64*wn)
    const float* Ab = A + (size_t)blockIdx.y * 128 * K;
    const float* Bb = B + (size_t)blockIdx.x * 128 * K;

    float acc[2][8][4];
#pragma unroll
    for (int mt = 0; mt < 2; mt++)
#pragma unroll
        for (int nt = 0; nt < 8; nt++)
#pragma unroll
            for (int r = 0; r < 4; r++) acc[mt][nt][r] = 0.f;

    for (int k0 = 0; k0 < K; k0 += GBK) {
#pragma unroll
        for (int i = 0; i < 4; i++) {
            int idx = tid + i * 256;          // 1024 float4 slots
            int row = idx >> 3;
            int c4 = (idx & 7) << 2;
            float4 a4 = *(const float4*)(Ab + (size_t)row * K + k0 + c4);
            float h0, l0, h1, l1, h2, l2, h3, l3;
            split_tf32(a4.x, h0, l0); split_tf32(a4.y, h1, l1);
            split_tf32(a4.z, h2, l2); split_tf32(a4.w, h3, l3);
            *(float4*)&Ah[row * GLD + c4] = make_float4(h0, h1, h2, h3);
            *(float4*)&Al[row * GLD + c4] = make_float4(l0, l1, l2, l3);
            float4 b4 = *(const float4*)(Bb + (size_t)row * K + k0 + c4);
            split_tf32(b4.x, h0, l0); split_tf32(b4.y, h1, l1);
            split_tf32(b4.z, h2, l2); split_tf32(b4.w, h3, l3);
            *(float4*)&Bh[row * GLD + c4] = make_float4(h0, h1, h2, h3);
            *(float4*)&Bl[row * GLD + c4] = make_float4(l0, l1, l2, l3);
        }
        __syncthreads();

#pragma unroll
        for (int ks = 0; ks < 4; ks++) {
            const int kk = ks * 8 + t4;
            uint32_t ah[2][4], al[2][4];
#pragma unroll
            for (int mt = 0; mt < 2; mt++) {
                const float* pa = Ah + (size_t)(wm * 32 + mt * 16 + g) * GLD + kk;
                ah[mt][0] = U(pa[0]);       ah[mt][1] = U(pa[8 * GLD]);
                ah[mt][2] = U(pa[4]);       ah[mt][3] = U(pa[8 * GLD + 4]);
                const float* pl = Al + (size_t)(wm * 32 + mt * 16 + g) * GLD + kk;
                al[mt][0] = U(pl[0]);       al[mt][1] = U(pl[8 * GLD]);
                al[mt][2] = U(pl[4]);       al[mt][3] = U(pl[8 * GLD + 4]);
            }
#pragma unroll
            for (int nt = 0; nt < 8; nt++) {
                const float* pb = Bh + (size_t)(wn * 64 + nt * 8 + g) * GLD + kk;
                uint32_t bh2[2] = {U(pb[0]), U(pb[4])};
                const float* pbl = Bl + (size_t)(wn * 64 + nt * 8 + g) * GLD + kk;
                uint32_t bl2[2] = {U(pbl[0]), U(pbl[4])};
                mma8(acc[0][nt], ah[0], bh2);
                mma8(acc[1][nt], ah[1], bh2);
                mma8(acc[0][nt], ah[0], bl2);
                mma8(acc[1][nt], ah[1], bl2);
                mma8(acc[0][nt], al[0], bh2);
                mma8(acc[1][nt], al[1], bh2);
            }
        }
        __syncthreads();
    }

#pragma unroll
    for (int mt = 0; mt < 2; mt++) {
        int r0 = blockIdx.y * 128 + wm * 32 + mt * 16 + g;
#pragma unroll
        for (int nt = 0; nt < 8; nt++) {
            int col = blockIdx.x * 128 + wn * 64 + nt * 8 + 2 * t4;
            *(float2*)&C[(size_t)r0 * N + col] =
                make_float2(acc[mt][nt][0], acc[mt][nt][1]);
            *(float2*)&C[(size_t)(r0 + 8) * N + col] =
                make_float2(acc[mt][nt][2], acc[mt][nt][3]);
        }
    }
}

// ---------------------------------------------------------------------------
// Per-(s,head) RMSNorm (+ optional weight) (+ optional RoPE). One warp/task.
// ---------------------------------------------------------------------------
__global__ void __launch_bounds__(128) norm_rope_kernel(
    const float* __restrict__ in, float* __restrict__ out,
    const float* __restrict__ w,
    const float* __restrict__ cosT, const float* __restrict__ sinT,
    int nheads, int use_rope)
{
    int task = blockIdx.x * 4 + (threadIdx.x >> 5);
    int lane = threadIdx.x & 31;
    if (task >= S_LEN * nheads) return;
    int s = task / nheads, h = task - s * nheads;

    const float* x = in + (size_t)s * (nheads * HD) + h * HD;
    float v0 = x[lane], v1 = x[lane + 32], v2 = x[lane + 64], v3 = x[lane + 96];
    float ss = v0 * v0 + v1 * v1 + v2 * v2 + v3 * v3;
#pragma unroll
    for (int o = 16; o > 0; o >>= 1) ss += __shfl_xor_sync(0xFFFFFFFFu, ss, o);
    float inv = rsqrtf(ss * (1.f / HD) + 1e-6f);
    float n0 = v0 * inv, n1 = v1 * inv, n2 = v2 * inv, n3 = v3 * inv;
    if (w) {
        n0 *= w[lane]; n1 *= w[lane + 32]; n2 *= w[lane + 64]; n3 *= w[lane + 96];
    }
    float o0 = n0, o1 = n1, o2 = n2, o3 = n3;
    if (use_rope) {
        const float* c  = cosT + (size_t)s * HD;
        const float* sn = sinT + (size_t)s * HD;
        o0 = n0 * c[lane]      - n2 * sn[lane];
        o1 = n1 * c[lane + 32] - n3 * sn[lane + 32];
        o2 = n2 * c[lane + 64] + n0 * sn[lane + 64];
        o3 = n3 * c[lane + 96] + n1 * sn[lane + 96];
    }
    float* y = out + ((size_t)h * S_LEN + s) * HD;
    y[lane] = o0; y[lane + 32] = o1; y[lane + 64] = o2; y[lane + 96] = o3;
}

// ---------------------------------------------------------------------------
// Causal flash attention via tf32 mma. Block = (64 q-rows, head). 256 thr.
// S = QK^T with 3xTF32 split; PV with single tf32 (error ~3e-4, suppressed).
// ---------------------------------------------------------------------------
#define AQLD 132
#define AVLD 136
#define APLD 68
#define ATTN_SMEM_FLOATS (4 * 64 * AQLD + 64 * AVLD + 64 * APLD + 3 * 64)

__global__ void __launch_bounds__(256) attn_mma_kernel(
    const float* __restrict__ Q, const float* __restrict__ K,
    const float* __restrict__ V, float* __restrict__ O)
{
    extern __shared__ float sm[];
    float* Qh = sm;
    float* Ql = Qh + 64 * AQLD;
    float* Kh = Ql + 64 * AQLD;
    float* Kl = Kh + 64 * AQLD;
    float* Vs = Kl + 64 * AQLD;           // [key][d], tf32-rounded
    float* Ps = Vs + 64 * AVLD;           // scores, then tf32 probs
    float* mrow = Ps + 64 * APLD;
    float* lrow = mrow + 64;
    float* arow = lrow + 64;

    const int rb = blockIdx.x, h = blockIdx.y, kvh = h >> 2;
    const int tid = threadIdx.x, w = tid >> 5, lane = tid & 31;
    const int g = lane >> 2, t4 = lane & 3;
    const int m0 = (w >> 1) * 16;         // warp row strip
    const int nh = (w & 1);               // n half

    const float* Qg = Q + ((size_t)h * S_LEN + rb * 64) * HD;
    const float* Kg = K + (size_t)kvh * S_LEN * HD;
    const float* Vg = V + (size_t)kvh * S_LEN * HD;

    // load Q (split hi/lo)
#pragma unroll
    for (int i = 0; i < 8; i++) {
        int idx = tid + i * 256;          // 2048 float4 slots
        int row = idx >> 5, c4 = (idx & 31) << 2;
        float4 q4 = *(const float4*)(Qg + (size_t)row * HD + c4);
        float h0, l0, h1, l1, h2, l2, h3, l3;
        split_tf32(q4.x, h0, l0); split_tf32(q4.y, h1, l1);
        split_tf32(q4.z, h2, l2); split_tf32(q4.w, h3, l3);
        *(float4*)&Qh[row * AQLD + c4] = make_float4(h0, h1, h2, h3);
        *(float4*)&Ql[row * AQLD + c4] = make_float4(l0, l1, l2, l3);
    }
    if (tid < 64) { mrow[tid] = -INFINITY; lrow[tid] = 0.f; }

    float oacc[8][4];
#pragma unroll
    for (int nt = 0; nt < 8; nt++)
#pragma unroll
        for (int r = 0; r < 4; r++) oacc[nt][r] = 0.f;

    for (int kb = 0; kb <= rb; kb++) {
        __syncthreads();     // prev PV done; Q/m/l visible on first iter
        const float* Kgb = Kg + (size_t)kb * 64 * HD;
        const float* Vgb = Vg + (size_t)kb * 64 * HD;
#pragma unroll
        for (int i = 0; i < 8; i++) {
            int idx = tid + i * 256;
            int row = idx >> 5, c4 = (idx & 31) << 2;
            float4 k4 = *(const float4*)(Kgb + (size_t)row * HD + c4);
            float h0, l0, h1, l1, h2, l2, h3, l3;
            split_tf32(k4.x, h0, l0); split_tf32(k4.y, h1, l1);
            split_tf32(k4.z, h2, l2); split_tf32(k4.w, h3, l3);
            *(float4*)&Kh[row * AQLD + c4] = make_float4(h0, h1, h2, h3);
            *(float4*)&Kl[row * AQLD + c4] = make_float4(l0, l1, l2, l3);
            float4 v4 = *(const float4*)(Vgb + (size_t)row * HD + c4);
            *(float4*)&Vs[row * AVLD + c4] = make_float4(
                __uint_as_float(f2tf(v4.x)), __uint_as_float(f2tf(v4.y)),
                __uint_as_float(f2tf(v4.z)), __uint_as_float(f2tf(v4.w)));
        }
        __syncthreads();

        // S = Q K^T  (warp: rows m0..m0+15, cols nh*32..nh*32+31)
        float sacc[4][4];
#pragma unroll
        for (int nt = 0; nt < 4; nt++)
#pragma unroll
            for (int r = 0; r < 4; r++) sacc[nt][r] = 0.f;

#pragma unroll
        for (int ks = 0; ks < 16; ks++) {
            const int kk = ks * 8 + t4;
            const float* pa = Qh + (size_t)(m0 + g) * AQLD + kk;
            uint32_t qhf[4] = {U(pa[0]), U(pa[8 * AQLD]), U(pa[4]), U(pa[8 * AQLD + 4])};
            const float* pl = Ql + (size_t)(m0 + g) * AQLD + kk;
            uint32_t qlf[4] = {U(pl[0]), U(pl[8 * AQLD]), U(pl[4]), U(pl[8 * AQLD + 4])};
#pragma unroll
            for (int nt = 0; nt < 4; nt++) {
                const float* pb = Kh + (size_t)(nh * 32 + nt * 8 + g) * AQLD + kk;
                uint32_t khf[2] = {U(pb[0]), U(pb[4])};
                const float* pbl = Kl + (size_t)(nh * 32 + nt * 8 + g) * AQLD + kk;
                uint32_t klf[2] = {U(pbl[0]), U(pbl[4])};
                mma8(sacc[nt], qhf, khf);
                mma8(sacc[nt], qhf, klf);
                mma8(sacc[nt], qlf, khf);
            }
        }
        // write S with causal mask
        const bool diag = (kb == rb);
#pragma unroll
        for (int nt = 0; nt < 4; nt++) {
            int cc = nh * 32 + nt * 8 + 2 * t4;
            int r0 = m0 + g, r1 = m0 + g + 8;
            float s0 = sacc[nt][0], s1 = sacc[nt][1];
            float s2 = sacc[nt][2], s3 = sacc[nt][3];
            if (diag) {
                if (cc > r0) s0 = -INFINITY;
                if (cc + 1 > r0) s1 = -INFINITY;
                if (cc > r1) s2 = -INFINITY;
                if (cc + 1 > r1) s3 = -INFINITY;
            }
            Ps[r0 * APLD + cc] = s0; Ps[r0 * APLD + cc + 1] = s1;
            Ps[r1 * APLD + cc] = s2; Ps[r1 * APLD + cc + 1] = s3;
        }
        __syncthreads();

        // online softmax: 4 threads per row (16 cols each)
        {
            int r = tid >> 2, seg = tid & 3;
            float* Pr = Ps + r * APLD + seg * 16;
            float mloc = -INFINITY;
#pragma unroll
            for (int c = 0; c < 16; c++) mloc = fmaxf(mloc, Pr[c]);
            mloc = fmaxf(mloc, __shfl_xor_sync(0xFFFFFFFFu, mloc, 1));
            mloc = fmaxf(mloc, __shfl_xor_sync(0xFFFFFFFFu, mloc, 2));
            float mold = mrow[r];
            float mnew = fmaxf(mold, mloc);
            float lsum = 0.f;
#pragma unroll
            for (int c = 0; c < 16; c++) {
                float p = __expf(Pr[c] - mnew);
                Pr[c] = __uint_as_float(f2tf(p));
                lsum += p;
            }
            lsum += __shfl_xor_sync(0xFFFFFFFFu, lsum, 1);
            lsum += __shfl_xor_sync(0xFFFFFFFFu, lsum, 2);
            if (seg == 0) {
                float alpha = __expf(mold - mnew);  // 0 on first block
                arow[r] = alpha; mrow[r] = mnew;
                lrow[r] = lrow[r] * alpha + lsum;
            }
        }
        __syncthreads();

        // rescale + O += P @ V  (warp: rows m0.., cols nh*64..+63)
        float aL = arow[m0 + g], aH = arow[m0 + g + 8];
#pragma unroll
        for (int nt = 0; nt < 8; nt++) {
            oacc[nt][0] *= aL; oacc[nt][1] *= aL;
            oacc[nt][2] *= aH; oacc[nt][3] *= aH;
        }
#pragma unroll
        for (int ks = 0; ks < 8; ks++) {
            const int kk = ks * 8 + t4;
            const float* pp = Ps + (size_t)(m0 + g) * APLD + kk;
            uint32_t pf[4] = {U(pp[0]), U(pp[8 * APLD]), U(pp[4]), U(pp[8 * APLD + 4])};
#pragma unroll
            for (int nt = 0; nt < 8; nt++) {
                int col = nh * 64 + nt * 8 + g;
                const float* pv = Vs + (size_t)kk * AVLD + col;
                uint32_t vf[2] = {U(pv[0]), U(pv[4 * AVLD])};
                mma8(oacc[nt], pf, vf);
            }
        }
    }

    // normalize + write O[s][h*128 + col]
    float lL = 1.f / lrow[m0 + g], lH = 1.f / lrow[m0 + g + 8];
#pragma unroll
    for (int nt = 0; nt < 8; nt++) {
        int col = h * HD + nh * 64 + nt * 8 + 2 * t4;
        int s0 = rb * 64 + m0 + g;
        *(float2*)&O[(size_t)s0 * HIDDEN + col] =
            make_float2(oacc[nt][0] * lL, oacc[nt][1] * lL);
        *(float2*)&O[(size_t)(s0 + 8) * HIDDEN + col] =
            make_float2(oacc[nt][2] * lH, oacc[nt][3] * lH);
    }
}

// ---------------------------------------------------------------------------
extern "C" void kernel_launch(void* const* d_in, const int* in_sizes, int n_in,
                              void* d_out, int out_size)
{
    const float* hs   = (const float*)d_in[0];
    const float* cosT = (const float*)d_in[1];
    const float* sinT = (const float*)d_in[2];
    // d_in[3] = attention_mask: pure causal, implemented directly (not read)
    const float* Wq = (const float*)d_in[4];
    const float* Wk = (const float*)d_in[5];
    const float* Wv = (const float*)d_in[6];
    const float* Wo = (const float*)d_in[7];
    const float* qw = (const float*)d_in[8];
    const float* kw = (const float*)d_in[9];
    float* out = (float*)d_out;

    float *qraw, *kraw, *vraw, *qn, *kn, *vn, *ao;
    cudaGetSymbolAddress((void**)&qraw, g_Qraw);
    cudaGetSymbolAddress((void**)&kraw, g_Kraw);
    cudaGetSymbolAddress((void**)&vraw, g_Vraw);
    cudaGetSymbolAddress((void**)&qn, g_Qn);
    cudaGetSymbolAddress((void**)&kn, g_Kn);
    cudaGetSymbolAddress((void**)&vn, g_Vn);
    cudaGetSymbolAddress((void**)&ao, g_AO);

    cudaFuncSetAttribute(gemm_tf32x3_kernel,
                         cudaFuncAttributeMaxDynamicSharedMemorySize, GEMM_SMEM_BYTES);
    size_t attn_smem = ATTN_SMEM_FLOATS * sizeof(float);
    cudaFuncSetAttribute(attn_mma_kernel,
                         cudaFuncAttributeMaxDynamicSharedMemorySize, (int)attn_smem);

    // QKV projections (tf32x3 tensor-core GEMM)
    gemm_tf32x3_kernel<<<dim3(HIDDEN / 128, S_LEN / 128), 256, GEMM_SMEM_BYTES>>>(
        hs, Wq, qraw, S_LEN, HIDDEN, HIDDEN);
    gemm_tf32x3_kernel<<<dim3(NKV * HD / 128, S_LEN / 128), 256, GEMM_SMEM_BYTES>>>(
        hs, Wk, kraw, S_LEN, NKV * HD, HIDDEN);
    gemm_tf32x3_kernel<<<dim3(NKV * HD / 128, S_LEN / 128), 256, GEMM_SMEM_BYTES>>>(
        hs, Wv, vraw, S_LEN, NKV * HD, HIDDEN);

    // RMSNorm (+RoPE) -> head-major layouts
    norm_rope_kernel<<<(S_LEN * NH + 3) / 4, 128>>>(qraw, qn, qw, cosT, sinT, NH, 1);
    norm_rope_kernel<<<(S_LEN * NKV + 3) / 4, 128>>>(kraw, kn, kw, cosT, sinT, NKV, 1);
    norm_rope_kernel<<<(S_LEN * NKV + 3) / 4, 128>>>(vraw, vn, nullptr, cosT, sinT, NKV, 0);

    // Causal GQA flash attention (tensor-core)
    attn_mma_kernel<<<dim3(S_LEN / 64, NH), 256, attn_smem>>>(qn, kn, vn, ao);

    // Output projection
    gemm_tf32x3_kernel<<<dim3(HIDDEN / 128, S_LEN / 128), 256, GEMM_SMEM_BYTES>>>(
        ao, Wo, out, S_LEN, HIDDEN, HIDDEN);
}

// round 3
// speedup vs baseline: 1.7394x; 1.0012x over previous
#include <cuda_runtime.h>
#include <cuda_bf16.h>
#include <math.h>
#include <stdint.h>

#define S_LEN 4096
#define HIDDEN 2048
#define NH 16
#define NKV 4
#define HD 128

// Scratch (device globals: allowed; runtime alloc is not)
__device__ float g_Qraw[S_LEN * HIDDEN];
__device__ float g_Kraw[S_LEN * NKV * HD];
__device__ float g_Vraw[S_LEN * NKV * HD];
__device__ float g_Qn[S_LEN * HIDDEN];      // [h][s][d]
__device__ float g_Kn[S_LEN * NKV * HD];    // [kv][s][d]
__device__ float g_Vn[S_LEN * NKV * HD];    // [kv][s][d]
__device__ float g_AO[S_LEN * HIDDEN];      // [s][h*128+d]

// ---------------------------------------------------------------------------
// tf32 helpers
// ---------------------------------------------------------------------------
__device__ __forceinline__ uint32_t f2tf(float x) {
    uint32_t r;
    asm("cvt.rna.tf32.f32 %0, %1;" : "=r"(r) : "f"(x));
    return r;
}
__device__ __forceinline__ void split_tf32(float x, float& h, float& l) {
    uint32_t hb;
    asm("cvt.rna.tf32.f32 %0, %1;" : "=r"(hb) : "f"(x));
    h = __uint_as_float(hb);
    float r = x - h;
    uint32_t lb;
    asm("cvt.rna.tf32.f32 %0, %1;" : "=r"(lb) : "f"(r));
    l = __uint_as_float(lb);
}
#define U(x) __float_as_uint(x)

// D += A(16x8) * B(8x8), tf32 inputs, f32 accum.
// A frag: a0=(g,t4) a1=(g+8,t4) a2=(g,t4+4) a3=(g+8,t4+4); g=lane>>2, t4=lane&3
// B frag: b0=(k=t4, n=g) b1=(k=t4+4, n=g)
// C frag: c0=(g,2t4) c1=(g,2t4+1) c2=(g+8,2t4) c3=(g+8,2t4+1)
__device__ __forceinline__ void mma8(float* c, const uint32_t* a, const uint32_t* b) {
    asm volatile(
        "mma.sync.aligned.m16n8k8.row.col.f32.tf32.tf32.f32 "
        "{%0,%1,%2,%3},{%4,%5,%6,%7},{%8,%9},{%0,%1,%2,%3};\n"
        : "+f"(c[0]), "+f"(c[1]), "+f"(c[2]), "+f"(c[3])
        : "r"(a[0]), "r"(a[1]), "r"(a[2]), "r"(a[3]), "r"(b[0]), "r"(b[1]));
}

// ---------------------------------------------------------------------------
// C[M,N] = A[M,K] @ B[N,K]^T via 3xTF32 mma. 128x128 block, k-chunk 32,
// 256 threads = 8 warps, warp tile 32(m) x 64(n).
// ---------------------------------------------------------------------------
#define GBK 32
#define GLD 36
#define GEMM_SMEM_BYTES (4 * 128 * GLD * 4)

__global__ void __launch_bounds__(256) gemm_tf32x3_kernel(
    const float* __restrict__ A, const float* __restrict__ B,
    float* __restrict__ C, int M, int N, int K)
{
    extern __shared__ float sm[];
    float* Ah = sm;
    float* Al = Ah + 128 * GLD;
    float* Bh = Al + 128 * GLD;
    float* Bl = Bh + 128 * GLD;

    const int tid = threadIdx.x, w = tid >> 5, lane = tid & 31;
    const int g = lane >> 2, t4 = lane & 3;
    const int wm = w >> 1, wn = w & 1;   // warp tile origin: (32*wm, 64*wn)
    const float* Ab = A + (size_t)blockIdx.y * 128 * K;
    const float* Bb = B + (size_t)blockIdx.x * 128 * K;

    float acc[2][8][4];
#pragma unroll
    for (int mt = 0; mt < 2; mt++)
#pragma unroll
        for (int nt = 0; nt < 8; nt++)
#pragma unroll
            for (int r = 0; r < 4; r++) acc[mt][nt][r] = 0.f;

    for (int k0 = 0; k0 < K; k0 += GBK) {
#pragma unroll
        for (int i = 0; i < 4; i++) {
            int idx = tid + i * 256;          // 1024 float4 slots
            int row = idx >> 3;
            int c4 = (idx & 7) << 2;
            float4 a4 = *(const float4*)(Ab + (size_t)row * K + k0 + c4);
            float h0, l0, h1, l1, h2, l2, h3, l3;
            split_tf32(a4.x, h0, l0); split_tf32(a4.y, h1, l1);
            split_tf32(a4.z, h2, l2); split_tf32(a4.w, h3, l3);
            *(float4*)&Ah[row * GLD + c4] = make_float4(h0, h1, h2, h3);
            *(float4*)&Al[row * GLD + c4] = make_float4(l0, l1, l2, l3);
            float4 b4 = *(const float4*)(Bb + (size_t)row * K + k0 + c4);
            split_tf32(b4.x, h0, l0); split_tf32(b4.y, h1, l1);
            split_tf32(b4.z, h2, l2); split_tf32(b4.w, h3, l3);
            *(float4*)&Bh[row * GLD + c4] = make_float4(h0, h1, h2, h3);
            *(float4*)&Bl[row * GLD + c4] = make_float4(l0, l1, l2, l3);
        }
        __syncthreads();

#pragma unroll
        for (int ks = 0; ks < 4; ks++) {
            const int kk = ks * 8 + t4;
            uint32_t ah[2][4], al[2][4];
#pragma unroll
            for (int mt = 0; mt < 2; mt++) {
                const float* pa = Ah + (size_t)(wm * 32 + mt * 16 + g) * GLD + kk;
                ah[mt][0] = U(pa[0]);       ah[mt][1] = U(pa[8 * GLD]);
                ah[mt][2] = U(pa[4]);       ah[mt][3] = U(pa[8 * GLD + 4]);
                const float* pl = Al + (size_t)(wm * 32 + mt * 16 + g) * GLD + kk;
                al[mt][0] = U(pl[0]);       al[mt][1] = U(pl[8 * GLD]);
                al[mt][2] = U(pl[4]);       al[mt][3] = U(pl[8 * GLD + 4]);
            }
#pragma unroll
            for (int nt = 0; nt < 8; nt++) {
                const float* pb = Bh + (size_t)(wn * 64 + nt * 8 + g) * GLD + kk;
                uint32_t bh2[2] = {U(pb[0]), U(pb[4])};
                const float* pbl = Bl + (size_t)(wn * 64 + nt * 8 + g) * GLD + kk;
                uint32_t bl2[2] = {U(pbl[0]), U(pbl[4])};
                mma8(acc[0][nt], ah[0], bh2);
                mma8(acc[1][nt], ah[1], bh2);
                mma8(acc[0][nt], ah[0], bl2);
                mma8(acc[1][nt], ah[1], bl2);
                mma8(acc[0][nt], al[0], bh2);
                mma8(acc[1][nt], al[1], bh2);
            }
        }
        __syncthreads();
    }

#pragma unroll
    for (int mt = 0; mt < 2; mt++) {
        int r0 = blockIdx.y * 128 + wm * 32 + mt * 16 + g;
#pragma unroll
        for (int nt = 0; nt < 8; nt++) {
            int col = blockIdx.x * 128 + wn * 64 + nt * 8 + 2 * t4;
            *(float2*)&C[(size_t)r0 * N + col] =
                make_float2(acc[mt][nt][0], acc[mt][nt][1]);
            *(float2*)&C[(size_t)(r0 + 8) * N + col] =
                make_float2(acc[mt][nt][2], acc[mt][nt][3]);
        }
    }
}

// ---------------------------------------------------------------------------
// Per-(s,head) RMSNorm (+ optional weight) (+ optional RoPE). One warp/task.
// ---------------------------------------------------------------------------
__global__ void __launch_bounds__(128) norm_rope_kernel(
    const float* __restrict__ in, float* __restrict__ out,
    const float* __restrict__ w,
    const float* __restrict__ cosT, const float* __restrict__ sinT,
    int nheads, int use_rope)
{
    int task = blockIdx.x * 4 + (threadIdx.x >> 5);
    int lane = threadIdx.x & 31;
    if (task >= S_LEN * nheads) return;
    int s = task / nheads, h = task - s * nheads;

    const float* x = in + (size_t)s * (nheads * HD) + h * HD;
    float v0 = x[lane], v1 = x[lane + 32], v2 = x[lane + 64], v3 = x[lane + 96];
    float ss = v0 * v0 + v1 * v1 + v2 * v2 + v3 * v3;
#pragma unroll
    for (int o = 16; o > 0; o >>= 1) ss += __shfl_xor_sync(0xFFFFFFFFu, ss, o);
    float inv = rsqrtf(ss * (1.f / HD) + 1e-6f);
    float n0 = v0 * inv, n1 = v1 * inv, n2 = v2 * inv, n3 = v3 * inv;
    if (w) {
        n0 *= w[lane]; n1 *= w[lane + 32]; n2 *= w[lane + 64]; n3 *= w[lane + 96];
    }
    float o0 = n0, o1 = n1, o2 = n2, o3 = n3;
    if (use_rope) {
        const float* c  = cosT + (size_t)s * HD;
        const float* sn = sinT + (size_t)s * HD;
        o0 = n0 * c[lane]      - n2 * sn[lane];
        o1 = n1 * c[lane + 32] - n3 * sn[lane + 32];
        o2 = n2 * c[lane + 64] + n0 * sn[lane + 64];
        o3 = n3 * c[lane + 96] + n1 * sn[lane + 96];
    }
    float* y = out + ((size_t)h * S_LEN + s) * HD;
    y[lane] = o0; y[lane + 32] = o1; y[lane + 64] = o2; y[lane + 96] = o3;
}

// ---------------------------------------------------------------------------
// Causal flash attention via tf32 mma. Block = (64 q-rows, head). 256 thr.
// S = QK^T with 3xTF32 split; PV with single tf32 (error ~3e-4, suppressed).
// ---------------------------------------------------------------------------
#define AQLD 132
#define AVLD 136
#define APLD 68
#define ATTN_SMEM_FLOATS (4 * 64 * AQLD + 64 * AVLD + 64 * APLD + 3 * 64)

__global__ void __launch_bounds__(256) attn_mma_kernel(
    const float* __restrict__ Q, const float* __restrict__ K,
    const float* __restrict__ V, float* __restrict__ O)
{
    extern __shared__ float sm[];
    float* Qh = sm;
    float* Ql = Qh + 64 * AQLD;
    float* Kh = Ql + 64 * AQLD;
    float* Kl = Kh + 64 * AQLD;
    float* Vs = Kl + 64 * AQLD;           // [key][d], tf32-rounded
    float* Ps = Vs + 64 * AVLD;           // scores, then tf32 probs
    float* mrow = Ps + 64 * APLD;
    float* lrow = mrow + 64;
    float* arow = lrow + 64;

    const int rb = blockIdx.x, h = blockIdx.y, kvh = h >> 2;
    const int tid = threadIdx.x, w = tid >> 5, lane = tid & 31;
    const int g = lane >> 2, t4 = lane & 3;
    const int m0 = (w >> 1) * 16;         // warp row strip
    const int nh = (w & 1);               // n half

    const float* Qg = Q + ((size_t)h * S_LEN + rb * 64) * HD;
    const float* Kg = K + (size_t)kvh * S_LEN * HD;
    const float* Vg = V + (size_t)kvh * S_LEN * HD;

    // load Q (split hi/lo)
#pragma unroll
    for (int i = 0; i < 8; i++) {
        int idx = tid + i * 256;          // 2048 float4 slots
        int row = idx >> 5, c4 = (idx & 31) << 2;
        float4 q4 = *(const float4*)(Qg + (size_t)row * HD + c4);
        float h0, l0, h1, l1, h2, l2, h3, l3;
        split_tf32(q4.x, h0, l0); split_tf32(q4.y, h1, l1);
        split_tf32(q4.z, h2, l2); split_tf32(q4.w, h3, l3);
        *(float4*)&Qh[row * AQLD + c4] = make_float4(h0, h1, h2, h3);
        *(float4*)&Ql[row * AQLD + c4] = make_float4(l0, l1, l2, l3);
    }
    if (tid < 64) { mrow[tid] = -INFINITY; lrow[tid] = 0.f; }

    float oacc[8][4];
#pragma unroll
    for (int nt = 0; nt < 8; nt++)
#pragma unroll
        for (int r = 0; r < 4; r++) oacc[nt][r] = 0.f;

    for (int kb = 0; kb <= rb; kb++) {
        __syncthreads();     // prev PV done; Q/m/l visible on first iter
        const float* Kgb = Kg + (size_t)kb * 64 * HD;
        const float* Vgb = Vg + (size_t)kb * 64 * HD;
#pragma unroll
        for (int i = 0; i < 8; i++) {
            int idx = tid + i * 256;
            int row = idx >> 5, c4 = (idx & 31) << 2;
            float4 k4 = *(const float4*)(Kgb + (size_t)row * HD + c4);
            float h0, l0, h1, l1, h2, l2, h3, l3;
            split_tf32(k4.x, h0, l0); split_tf32(k4.y, h1, l1);
            split_tf32(k4.z, h2, l2); split_tf32(k4.w, h3, l3);
            *(float4*)&Kh[row * AQLD + c4] = make_float4(h0, h1, h2, h3);
            *(float4*)&Kl[row * AQLD + c4] = make_float4(l0, l1, l2, l3);
            float4 v4 = *(const float4*)(Vgb + (size_t)row * HD + c4);
            *(float4*)&Vs[row * AVLD + c4] = make_float4(
                __uint_as_float(f2tf(v4.x)), __uint_as_float(f2tf(v4.y)),
                __uint_as_float(f2tf(v4.z)), __uint_as_float(f2tf(v4.w)));
        }
        __syncthreads();

        // S = Q K^T  (warp: rows m0..m0+15, cols nh*32..nh*32+31)
        float sacc[4][4];
#pragma unroll
        for (int nt = 0; nt < 4; nt++)
#pragma unroll
            for (int r = 0; r < 4; r++) sacc[nt][r] = 0.f;

#pragma unroll
        for (int ks = 0; ks < 16; ks++) {
            const int kk = ks * 8 + t4;
            const float* pa = Qh + (size_t)(m0 + g) * AQLD + kk;
            uint32_t qhf[4] = {U(pa[0]), U(pa[8 * AQLD]), U(pa[4]), U(pa[8 * AQLD + 4])};
            const float* pl = Ql + (size_t)(m0 + g) * AQLD + kk;
            uint32_t qlf[4] = {U(pl[0]), U(pl[8 * AQLD]), U(pl[4]), U(pl[8 * AQLD + 4])};
#pragma unroll
            for (int nt = 0; nt < 4; nt++) {
                const float* pb = Kh + (size_t)(nh * 32 + nt * 8 + g) * AQLD + kk;
                uint32_t khf[2] = {U(pb[0]), U(pb[4])};
                const float* pbl = Kl + (size_t)(nh * 32 + nt * 8 + g) * AQLD + kk;
                uint32_t klf[2] = {U(pbl[0]), U(pbl[4])};
                mma8(sacc[nt], qhf, khf);
                mma8(sacc[nt], qhf, klf);
                mma8(sacc[nt], qlf, khf);
            }
        }
        // write S with causal mask
        const bool diag = (kb == rb);
#pragma unroll
        for (int nt = 0; nt < 4; nt++) {
            int cc = nh * 32 + nt * 8 + 2 * t4;
            int r0 = m0 + g, r1 = m0 + g + 8;
            float s0 = sacc[nt][0], s1 = sacc[nt][1];
            float s2 = sacc[nt][2], s3 = sacc[nt][3];
            if (diag) {
                if (cc > r0) s0 = -INFINITY;
                if (cc + 1 > r0) s1 = -INFINITY;
                if (cc > r1) s2 = -INFINITY;
                if (cc + 1 > r1) s3 = -INFINITY;
            }
            Ps[r0 * APLD + cc] = s0; Ps[r0 * APLD + cc + 1] = s1;
            Ps[r1 * APLD + cc] = s2; Ps[r1 * APLD + cc + 1] = s3;
        }
        __syncthreads();

        // online softmax: 4 threads per row (16 cols each)
        {
            int r = tid >> 2, seg = tid & 3;
            float* Pr = Ps + r * APLD + seg * 16;
            float mloc = -INFINITY;
#pragma unroll
            for (int c = 0; c < 16; c++) mloc = fmaxf(mloc, Pr[c]);
            mloc = fmaxf(mloc, __shfl_xor_sync(0xFFFFFFFFu, mloc, 1));
            mloc = fmaxf(mloc, __shfl_xor_sync(0xFFFFFFFFu, mloc, 2));
            float mold = mrow[r];
            float mnew = fmaxf(mold, mloc);
            float lsum = 0.f;
#pragma unroll
            for (int c = 0; c < 16; c++) {
                float p = __expf(Pr[c] - mnew);
                Pr[c] = __uint_as_float(f2tf(p));
                lsum += p;
            }
            lsum += __shfl_xor_sync(0xFFFFFFFFu, lsum, 1);
            lsum += __shfl_xor_sync(0xFFFFFFFFu, lsum, 2);
            if (seg == 0) {
                float alpha = __expf(mold - mnew);  // 0 on first block
                arow[r] = alpha; mrow[r] = mnew;
                lrow[r] = lrow[r] * alpha + lsum;
            }
        }
        __syncthreads();

        // rescale + O += P @ V  (warp: rows m0.., cols nh*64..+63)
        float aL = arow[m0 + g], aH = arow[m0 + g + 8];
#pragma unroll
        for (int nt = 0; nt < 8; nt++) {
            oacc[nt][0] *= aL; oacc[nt][1] *= aL;
            oacc[nt][2] *= aH; oacc[nt][3] *= aH;
        }
#pragma unroll
        for (int ks = 0; ks < 8; ks++) {
            const int kk = ks * 8 + t4;
            const float* pp = Ps + (size_t)(m0 + g) * APLD + kk;
            uint32_t pf[4] = {U(pp[0]), U(pp[8 * APLD]), U(pp[4]), U(pp[8 * APLD + 4])};
#pragma unroll
            for (int nt = 0; nt < 8; nt++) {
                int col = nh * 64 + nt * 8 + g;
                const float* pv = Vs + (size_t)kk * AVLD + col;
                uint32_t vf[2] = {U(pv[0]), U(pv[4 * AVLD])};
                mma8(oacc[nt], pf, vf);
            }
        }
    }

    // normalize + write O[s][h*128 + col]
    float lL = 1.f / lrow[m0 + g], lH = 1.f / lrow[m0 + g + 8];
#pragma unroll
    for (int nt = 0; nt < 8; nt++) {
        int col = h * HD + nh * 64 + nt * 8 + 2 * t4;
        int s0 = rb * 64 + m0 + g;
        *(float2*)&O[(size_t)s0 * HIDDEN + col] =
            make_float2(oacc[nt][0] * lL, oacc[nt][1] * lL);
        *(float2*)&O[(size_t)(s0 + 8) * HIDDEN + col] =
            make_float2(oacc[nt][2] * lH, oacc[nt][3] * lH);
    }
}

// ---------------------------------------------------------------------------
extern "C" void kernel_launch(void* const* d_in, const int* in_sizes, int n_in,
                              void* d_out, int out_size)
{
    const float* hs   = (const float*)d_in[0];
    const float* cosT = (const float*)d_in[1];
    const float* sinT = (const float*)d_in[2];
    // d_in[3] = attention_mask: pure causal, implemented directly (not read)
    const float* Wq = (const float*)d_in[4];
    const float* Wk = (const float*)d_in[5];
    const float* Wv = (const float*)d_in[6];
    const float* Wo = (const float*)d_in[7];
    const float* qw = (const float*)d_in[8];
    const float* kw = (const float*)d_in[9];
    float* out = (float*)d_out;

    float *qraw, *kraw, *vraw, *qn, *kn, *vn, *ao;
    cudaGetSymbolAddress((void**)&qraw, g_Qraw);
    cudaGetSymbolAddress((void**)&kraw, g_Kraw);
    cudaGetSymbolAddress((void**)&vraw, g_Vraw);
    cudaGetSymbolAddress((void**)&qn, g_Qn);
    cudaGetSymbolAddress((void**)&kn, g_Kn);
    cudaGetSymbolAddress((void**)&vn, g_Vn);
    cudaGetSymbolAddress((void**)&ao, g_AO);

    cudaFuncSetAttribute(gemm_tf32x3_kernel,
                         cudaFuncAttributeMaxDynamicSharedMemorySize, GEMM_SMEM_BYTES);
    size_t attn_smem = ATTN_SMEM_FLOATS * sizeof(float);
    cudaFuncSetAttribute(attn_mma_kernel,
                         cudaFuncAttributeMaxDynamicSharedMemorySize, (int)attn_smem);

    // QKV projections (tf32x3 tensor-core GEMM)
    gemm_tf32x3_kernel<<<dim3(HIDDEN / 128, S_LEN / 128), 256, GEMM_SMEM_BYTES>>>(
        hs, Wq, qraw, S_LEN, HIDDEN, HIDDEN);
    gemm_tf32x3_kernel<<<dim3(NKV * HD / 128, S_LEN / 128), 256, GEMM_SMEM_BYTES>>>(
        hs, Wk, kraw, S_LEN, NKV * HD, HIDDEN);
    gemm_tf32x3_kernel<<<dim3(NKV * HD / 128, S_LEN / 128), 256, GEMM_SMEM_BYTES>>>(
        hs, Wv, vraw, S_LEN, NKV * HD, HIDDEN);

    // RMSNorm (+RoPE) -> head-major layouts
    norm_rope_kernel<<<(S_LEN * NH + 3) / 4, 128>>>(qraw, qn, qw, cosT, sinT, NH, 1);
    norm_rope_kernel<<<(S_LEN * NKV + 3) / 4, 128>>>(kraw, kn, kw, cosT, sinT, NKV, 1);
    norm_rope_kernel<<<(S_LEN * NKV + 3) / 4, 128>>>(vraw, vn, nullptr, cosT, sinT, NKV, 0);

    // Causal GQA flash attention (tensor-core)
    attn_mma_kernel<<<dim3(S_LEN / 64, NH), 256, attn_smem>>>(qn, kn, vn, ao);

    // Output projection
    gemm_tf32x3_kernel<<<dim3(HIDDEN / 128, S_LEN / 128), 256, GEMM_SMEM_BYTES>>>(
        ao, Wo, out, S_LEN, HIDDEN, HIDDEN);
}

// round 4
// speedup vs baseline: 3.4095x; 1.9601x over previous
#include <cuda_runtime.h>
#include <cuda_fp16.h>
#include <math.h>
#include <stdint.h>

#define S_LEN 4096
#define HIDDEN 2048
#define NH 16
#define NKV 4
#define HD 128

// ---------------- device-global scratch (no runtime alloc allowed) ----------
__device__ float g_Qraw[S_LEN * HIDDEN];
__device__ float g_Kraw[S_LEN * NKV * HD];
__device__ float g_Vraw[S_LEN * NKV * HD];

__device__ __half g_hsH[S_LEN * HIDDEN],   g_hsL[S_LEN * HIDDEN];
__device__ __half g_WqH[HIDDEN * HIDDEN],  g_WqL[HIDDEN * HIDDEN];
__device__ __half g_WkH[NKV * HD * HIDDEN], g_WkL[NKV * HD * HIDDEN];
__device__ __half g_WvH[NKV * HD * HIDDEN], g_WvL[NKV * HD * HIDDEN];
__device__ __half g_WoH[HIDDEN * HIDDEN],  g_WoL[HIDDEN * HIDDEN];

__device__ __half g_QnH[NH * S_LEN * HD],  g_QnL[NH * S_LEN * HD];   // [h][s][d]
__device__ __half g_KnH[NKV * S_LEN * HD], g_KnL[NKV * S_LEN * HD];  // [kv][s][d]
__device__ __half g_VnT[NKV * HD * S_LEN];                           // [kv][d][s]
__device__ __half g_AOH[S_LEN * HIDDEN],   g_AOL[S_LEN * HIDDEN];    // [s][hid]

// ---------------- helpers ---------------------------------------------------
__device__ __forceinline__ uint32_t ld32(const __half* p) {
    return *(const uint32_t*)p;
}
__device__ __forceinline__ void split16(float x, __half& hi, __half& lo) {
    hi = __float2half_rn(x);
    lo = __float2half_rn(x - __half2float(hi));
}
__device__ __forceinline__ void cp16(uint32_t dst, const void* src) {
    asm volatile("cp.async.cg.shared.global [%0], [%1], 16;\n" :: "r"(dst), "l"(src));
}
__device__ __forceinline__ void cp_commit() {
    asm volatile("cp.async.commit_group;\n");
}
template <int N>
__device__ __forceinline__ void cp_wait() {
    asm volatile("cp.async.wait_group %0;\n" :: "n"(N));
}
// fp16 m16n8k16, fp32 accum.
// A: a0=(g, k=2t4..+1) a1=(g+8, same) a2=(g, k+8) a3=(g+8, k+8)
// B: b0=(k=2t4..+1, n=g) b1=(k+8, n=g)
// C: c0,c1=(g, 2t4,2t4+1)  c2,c3=(g+8, ...)
__device__ __forceinline__ void mma16(float* c, const uint32_t* a, const uint32_t* b) {
    asm volatile(
        "mma.sync.aligned.m16n8k16.row.col.f32.f16.f16.f32 "
        "{%0,%1,%2,%3},{%4,%5,%6,%7},{%8,%9},{%0,%1,%2,%3};\n"
        : "+f"(c[0]), "+f"(c[1]), "+f"(c[2]), "+f"(c[3])
        : "r"(a[0]), "r"(a[1]), "r"(a[2]), "r"(a[3]), "r"(b[0]), "r"(b[1]));
}

// ---------------- split fp32 -> fp16 hi/lo ----------------------------------
__global__ void __launch_bounds__(256) split_kernel(
    const float* __restrict__ in, __half* __restrict__ hi,
    __half* __restrict__ lo, int n4)
{
    int i = blockIdx.x * 256 + threadIdx.x;
    if (i >= n4) return;
    float4 v = ((const float4*)in)[i];
    __half h0, l0, h1, l1, h2, l2, h3, l3;
    split16(v.x, h0, l0); split16(v.y, h1, l1);
    split16(v.z, h2, l2); split16(v.w, h3, l3);
    ((__half2*)hi)[2 * i]     = __halves2half2(h0, h1);
    ((__half2*)hi)[2 * i + 1] = __halves2half2(h2, h3);
    ((__half2*)lo)[2 * i]     = __halves2half2(l0, l1);
    ((__half2*)lo)[2 * i + 1] = __halves2half2(l2, l3);
}

// ---------------- fp16x3 GEMM: C[M,N] = A[M,K] @ B[N,K]^T -------------------
// 128x128 block, 256 thr (8 warps, 32x64 warp tiles), k-chunk 32, 3-stage
// cp.async pipeline. A,B given as fp16 hi/lo pairs; C fp32.
#define GK 32
#define GLDH 40                       // halves per smem row (32 + 8 pad)
#define GST 3
#define GARR (128 * GLDH)             // halves per array per stage
#define GSTAGE (4 * GARR)             // Ah, Al, Bh, Bl
#define GEMM_SMEM_BYTES (GST * GSTAGE * 2)

__global__ void __launch_bounds__(256) gemm_fp16x3(
    const __half* __restrict__ Ah, const __half* __restrict__ Al,
    const __half* __restrict__ Bh, const __half* __restrict__ Bl,
    float* __restrict__ C, int M, int N, int K)
{
    extern __shared__ __half smh[];
    uint32_t sbase = (uint32_t)__cvta_generic_to_shared(smh);
    const int tid = threadIdx.x, w = tid >> 5, lane = tid & 31;
    const int g = lane >> 2, t4 = lane & 3;
    const int wm = w >> 1, wn = w & 1;
    const __half* A0h = Ah + (size_t)blockIdx.y * 128 * K;
    const __half* A0l = Al + (size_t)blockIdx.y * 128 * K;
    const __half* B0h = Bh + (size_t)blockIdx.x * 128 * K;
    const __half* B0l = Bl + (size_t)blockIdx.x * 128 * K;
    const int nch = K / GK;

    float acc[2][8][4];
#pragma unroll
    for (int mt = 0; mt < 2; mt++)
#pragma unroll
        for (int nt = 0; nt < 8; nt++)
#pragma unroll
            for (int r = 0; r < 4; r++) acc[mt][nt][r] = 0.f;

    auto issue = [&](int chunk) {
        int st = chunk % GST;
        uint32_t sb = sbase + (uint32_t)(st * GSTAGE * 2);
        int k0 = chunk * GK;
#pragma unroll
        for (int j = 0; j < 2; j++) {
            int c = tid + j * 256;            // 0..511
            int row = c >> 2, seg = c & 3;    // seg: 16B chunk (8 halves)
            size_t go = (size_t)row * K + k0 + seg * 8;
            uint32_t so = (uint32_t)(row * GLDH + seg * 8) * 2;
            cp16(sb + 0 * GARR * 2 + so, A0h + go);
            cp16(sb + 1 * GARR * 2 + so, A0l + go);
            cp16(sb + 2 * GARR * 2 + so, B0h + go);
            cp16(sb + 3 * GARR * 2 + so, B0l + go);
        }
    };

    issue(0); cp_commit();
    issue(1); cp_commit();

    for (int i = 0; i < nch; i++) {
        if (i + 2 < nch) issue(i + 2);
        cp_commit();
        cp_wait<2>();
        __syncthreads();
        const __half* S   = smh + (i % GST) * GSTAGE;
        const __half* SAh = S;
        const __half* SAl = S + GARR;
        const __half* SBh = S + 2 * GARR;
        const __half* SBl = S + 3 * GARR;
#pragma unroll
        for (int ks = 0; ks < 2; ks++) {
            uint32_t ah[2][4], al[2][4];
#pragma unroll
            for (int mt = 0; mt < 2; mt++) {
                const __half* p = SAh + (wm * 32 + mt * 16 + g) * GLDH + ks * 16 + t4 * 2;
                ah[mt][0] = ld32(p);
                ah[mt][1] = ld32(p + 8 * GLDH);
                ah[mt][2] = ld32(p + 8);
                ah[mt][3] = ld32(p + 8 * GLDH + 8);
                const __half* q = SAl + (wm * 32 + mt * 16 + g) * GLDH + ks * 16 + t4 * 2;
                al[mt][0] = ld32(q);
                al[mt][1] = ld32(q + 8 * GLDH);
                al[mt][2] = ld32(q + 8);
                al[mt][3] = ld32(q + 8 * GLDH + 8);
            }
#pragma unroll
            for (int nt = 0; nt < 8; nt++) {
                const __half* pb = SBh + (wn * 64 + nt * 8 + g) * GLDH + ks * 16 + t4 * 2;
                uint32_t bh2[2] = {ld32(pb), ld32(pb + 8)};
                const __half* pl = SBl + (wn * 64 + nt * 8 + g) * GLDH + ks * 16 + t4 * 2;
                uint32_t bl2[2] = {ld32(pl), ld32(pl + 8)};
                mma16(acc[0][nt], ah[0], bh2);
                mma16(acc[1][nt], ah[1], bh2);
                mma16(acc[0][nt], ah[0], bl2);
                mma16(acc[1][nt], ah[1], bl2);
                mma16(acc[0][nt], al[0], bh2);
                mma16(acc[1][nt], al[1], bh2);
            }
        }
        __syncthreads();
    }

#pragma unroll
    for (int mt = 0; mt < 2; mt++) {
        int r0 = blockIdx.y * 128 + wm * 32 + mt * 16 + g;
#pragma unroll
        for (int nt = 0; nt < 8; nt++) {
            int col = blockIdx.x * 128 + wn * 64 + nt * 8 + 2 * t4;
            *(float2*)&C[(size_t)r0 * N + col] =
                make_float2(acc[mt][nt][0], acc[mt][nt][1]);
            *(float2*)&C[(size_t)(r0 + 8) * N + col] =
                make_float2(acc[mt][nt][2], acc[mt][nt][3]);
        }
    }
}

// ---------------- RMSNorm (+RoPE) -> fp16 outputs ---------------------------
// mode 1: weight + RoPE, out [h][s][d] hi/lo.  mode 0 (V): plain norm,
// single fp16, transposed out [h][d][s].
__global__ void __launch_bounds__(128) norm_rope_fp16(
    const float* __restrict__ in, __half* __restrict__ outH,
    __half* __restrict__ outL, const float* __restrict__ w,
    const float* __restrict__ cosT, const float* __restrict__ sinT,
    int nheads, int mode)
{
    int task = blockIdx.x * 4 + (threadIdx.x >> 5);
    int lane = threadIdx.x & 31;
    if (task >= S_LEN * nheads) return;
    int s = task / nheads, hh = task - s * nheads;

    const float* x = in + (size_t)s * (nheads * HD) + hh * HD;
    float v0 = x[lane], v1 = x[lane + 32], v2 = x[lane + 64], v3 = x[lane + 96];
    float ss = v0 * v0 + v1 * v1 + v2 * v2 + v3 * v3;
#pragma unroll
    for (int o = 16; o > 0; o >>= 1) ss += __shfl_xor_sync(0xFFFFFFFFu, ss, o);
    float inv = rsqrtf(ss * (1.f / HD) + 1e-6f);
    float n0 = v0 * inv, n1 = v1 * inv, n2 = v2 * inv, n3 = v3 * inv;

    if (mode) {
        n0 *= w[lane]; n1 *= w[lane + 32]; n2 *= w[lane + 64]; n3 *= w[lane + 96];
        const float* c  = cosT + (size_t)s * HD;
        const float* sn = sinT + (size_t)s * HD;
        float o0 = n0 * c[lane]      - n2 * sn[lane];
        float o1 = n1 * c[lane + 32] - n3 * sn[lane + 32];
        float o2 = n2 * c[lane + 64] + n0 * sn[lane + 64];
        float o3 = n3 * c[lane + 96] + n1 * sn[lane + 96];
        __half ah, al;
        __half* yh = outH + ((size_t)hh * S_LEN + s) * HD;
        __half* yl = outL + ((size_t)hh * S_LEN + s) * HD;
        split16(o0, ah, al); yh[lane] = ah;      yl[lane] = al;
        split16(o1, ah, al); yh[lane + 32] = ah; yl[lane + 32] = al;
        split16(o2, ah, al); yh[lane + 64] = ah; yl[lane + 64] = al;
        split16(o3, ah, al); yh[lane + 96] = ah; yl[lane + 96] = al;
    } else {
        __half* y = outH + (size_t)hh * HD * S_LEN;
        y[(size_t)(lane)      * S_LEN + s] = __float2half_rn(n0);
        y[(size_t)(lane + 32) * S_LEN + s] = __float2half_rn(n1);
        y[(size_t)(lane + 64) * S_LEN + s] = __float2half_rn(n2);
        y[(size_t)(lane + 96) * S_LEN + s] = __float2half_rn(n3);
    }
}

// ---------------- causal GQA flash attention, fp16 MMA ----------------------
// Block: 128 q-rows x head. 256 thr = 8 warps; warp tile 32 rows x half cols.
// QK^T fp16x3; softmax in registers; PV single fp16.
#define ALDQ 136
#define ALDV 72
#define OFF_QH 0
#define OFF_QL (128 * ALDQ)
#define OFF_KH (OFF_QL + 128 * ALDQ)
#define OFF_KL (OFF_KH + 64 * ALDQ)
#define OFF_VT (OFF_KL + 64 * ALDQ)
#define OFF_PP (OFF_VT + 128 * ALDV)
#define HALVES_TOT (OFF_PP + 128 * ALDV)
#define ATTN_SMEM_BYTES (HALVES_TOT * 2 + (2 * 128 + 2 * 128 + 128 + 128) * 4)

__global__ void __launch_bounds__(256) attn_fp16_kernel(
    const __half* __restrict__ Qh_g, const __half* __restrict__ Ql_g,
    const __half* __restrict__ Kh_g, const __half* __restrict__ Kl_g,
    const __half* __restrict__ Vt_g,
    __half* __restrict__ AOh, __half* __restrict__ AOl)
{
    extern __shared__ __half sm[];
    __half* Qh = sm + OFF_QH;
    __half* Ql = sm + OFF_QL;
    __half* Kh = sm + OFF_KH;
    __half* Kl = sm + OFF_KL;
    __half* Vt = sm + OFF_VT;
    __half* Pp = sm + OFF_PP;
    float* pmax  = (float*)(sm + HALVES_TOT);     // [2][128]
    float* plsum = pmax + 2 * 128;                // [2][128]
    float* mrow  = plsum + 2 * 128;               // [128]
    float* lrow  = mrow + 128;                    // [128]

    const int rb = blockIdx.x, hq = blockIdx.y, kvh = hq >> 2;
    const int tid = threadIdx.x, w = tid >> 5, lane = tid & 31;
    const int g = lane >> 2, t4 = lane & 3;
    const int m0 = (w >> 1) * 32;   // 32-row strip
    const int nh = w & 1;           // column half

    const __half* Qg_h = Qh_g + ((size_t)hq * S_LEN + rb * 128) * HD;
    const __half* Qg_l = Ql_g + ((size_t)hq * S_LEN + rb * 128) * HD;
    const __half* Kg_h = Kh_g + (size_t)kvh * S_LEN * HD;
    const __half* Kg_l = Kl_g + (size_t)kvh * S_LEN * HD;
    const __half* Vg   = Vt_g + (size_t)kvh * HD * S_LEN;

    // Q tiles (hi/lo), 128x128 halves each
#pragma unroll
    for (int j = 0; j < 8; j++) {
        int c = tid + j * 256;            // 0..2047
        int row = c >> 4, seg = c & 15;
        *(uint4*)&Qh[row * ALDQ + seg * 8] =
            *(const uint4*)(Qg_h + (size_t)row * HD + seg * 8);
        *(uint4*)&Ql[row * ALDQ + seg * 8] =
            *(const uint4*)(Qg_l + (size_t)row * HD + seg * 8);
    }
    if (tid < 128) { mrow[tid] = -INFINITY; lrow[tid] = 0.f; }

    float oacc[2][8][4];
#pragma unroll
    for (int mt = 0; mt < 2; mt++)
#pragma unroll
        for (int nt = 0; nt < 8; nt++)
#pragma unroll
            for (int r = 0; r < 4; r++) oacc[mt][nt][r] = 0.f;

    const int kbmax = 2 * rb + 1;
    for (int kb = 0; kb <= kbmax; kb++) {
        __syncthreads();   // prev iter fully done before overwriting tiles
        // K hi/lo (64x128) + Vt (128x64)
#pragma unroll
        for (int j = 0; j < 4; j++) {
            int c = tid + j * 256;            // 0..1023
            int row = c >> 4, seg = c & 15;
            size_t go = (size_t)(kb * 64 + row) * HD + seg * 8;
            *(uint4*)&Kh[row * ALDQ + seg * 8] = *(const uint4*)(Kg_h + go);
            *(uint4*)&Kl[row * ALDQ + seg * 8] = *(const uint4*)(Kg_l + go);
            int vrow = c >> 3, vseg = c & 7;
            *(uint4*)&Vt[vrow * ALDV + vseg * 8] =
                *(const uint4*)(Vg + (size_t)vrow * S_LEN + kb * 64 + vseg * 8);
        }
        __syncthreads();

        // ---- S = Q K^T (fp16x3) ----
        float sacc[2][4][4];
#pragma unroll
        for (int mt = 0; mt < 2; mt++)
#pragma unroll
            for (int nt = 0; nt < 4; nt++)
#pragma unroll
                for (int r = 0; r < 4; r++) sacc[mt][nt][r] = 0.f;

#pragma unroll
        for (int ks = 0; ks < 8; ks++) {
            uint32_t ah[2][4], al[2][4];
#pragma unroll
            for (int mt = 0; mt < 2; mt++) {
                const __half* p = Qh + (m0 + mt * 16 + g) * ALDQ + ks * 16 + t4 * 2;
                ah[mt][0] = ld32(p);
                ah[mt][1] = ld32(p + 8 * ALDQ);
                ah[mt][2] = ld32(p + 8);
                ah[mt][3] = ld32(p + 8 * ALDQ + 8);
                const __half* q = Ql + (m0 + mt * 16 + g) * ALDQ + ks * 16 + t4 * 2;
                al[mt][0] = ld32(q);
                al[mt][1] = ld32(q + 8 * ALDQ);
                al[mt][2] = ld32(q + 8);
                al[mt][3] = ld32(q + 8 * ALDQ + 8);
            }
#pragma unroll
            for (int nt = 0; nt < 4; nt++) {
                const __half* pb = Kh + (nh * 32 + nt * 8 + g) * ALDQ + ks * 16 + t4 * 2;
                uint32_t bh2[2] = {ld32(pb), ld32(pb + 8)};
                const __half* pl = Kl + (nh * 32 + nt * 8 + g) * ALDQ + ks * 16 + t4 * 2;
                uint32_t bl2[2] = {ld32(pl), ld32(pl + 8)};
                mma16(sacc[0][nt], ah[0], bh2);
                mma16(sacc[1][nt], ah[1], bh2);
                mma16(sacc[0][nt], ah[0], bl2);
                mma16(sacc[1][nt], ah[1], bl2);
                mma16(sacc[0][nt], al[0], bh2);
                mma16(sacc[1][nt], al[1], bh2);
            }
        }

        // ---- causal mask (register-level) ----
        if (kb >= 2 * rb) {
#pragma unroll
            for (int mt = 0; mt < 2; mt++) {
                int r0 = rb * 128 + m0 + mt * 16 + g;
                int r1 = r0 + 8;
#pragma unroll
                for (int nt = 0; nt < 4; nt++) {
                    int c0 = kb * 64 + nh * 32 + nt * 8 + 2 * t4;
                    if (c0 > r0)     sacc[mt][nt][0] = -INFINITY;
                    if (c0 + 1 > r0) sacc[mt][nt][1] = -INFINITY;
                    if (c0 > r1)     sacc[mt][nt][2] = -INFINITY;
                    if (c0 + 1 > r1) sacc[mt][nt][3] = -INFINITY;
                }
            }
        }

        // ---- per-warp row max -> pmax[nh][row] ----
#pragma unroll
        for (int mt = 0; mt < 2; mt++) {
            float rmL = -INFINITY, rmH = -INFINITY;
#pragma unroll
            for (int nt = 0; nt < 4; nt++) {
                rmL = fmaxf(rmL, fmaxf(sacc[mt][nt][0], sacc[mt][nt][1]));
                rmH = fmaxf(rmH, fmaxf(sacc[mt][nt][2], sacc[mt][nt][3]));
            }
            rmL = fmaxf(rmL, __shfl_xor_sync(0xFFFFFFFFu, rmL, 1));
            rmL = fmaxf(rmL, __shfl_xor_sync(0xFFFFFFFFu, rmL, 2));
            rmH = fmaxf(rmH, __shfl_xor_sync(0xFFFFFFFFu, rmH, 1));
            rmH = fmaxf(rmH, __shfl_xor_sync(0xFFFFFFFFu, rmH, 2));
            if (t4 == 0) {
                pmax[nh * 128 + m0 + mt * 16 + g]     = rmL;
                pmax[nh * 128 + m0 + mt * 16 + g + 8] = rmH;
            }
        }
        __syncthreads();

        // ---- p = exp(s-mnew); rescale oacc; Pp fp16; lsum partials ----
#pragma unroll
        for (int mt = 0; mt < 2; mt++) {
            int rL = m0 + mt * 16 + g, rH = rL + 8;
            float moL = mrow[rL];
            float mnL = fmaxf(moL, fmaxf(pmax[rL], pmax[128 + rL]));
            float aL  = __expf(moL - mnL);
            float moH = mrow[rH];
            float mnH = fmaxf(moH, fmaxf(pmax[rH], pmax[128 + rH]));
            float aH  = __expf(moH - mnH);
            float lsL = 0.f, lsH = 0.f;
#pragma unroll
            for (int nt = 0; nt < 4; nt++) {
                float p0 = __expf(sacc[mt][nt][0] - mnL);
                float p1 = __expf(sacc[mt][nt][1] - mnL);
                float p2 = __expf(sacc[mt][nt][2] - mnH);
                float p3 = __expf(sacc[mt][nt][3] - mnH);
                lsL += p0 + p1; lsH += p2 + p3;
                int ct = nh * 32 + nt * 8 + 2 * t4;
                *(__half2*)&Pp[rL * ALDV + ct] =
                    __halves2half2(__float2half_rn(p0), __float2half_rn(p1));
                *(__half2*)&Pp[rH * ALDV + ct] =
                    __halves2half2(__float2half_rn(p2), __float2half_rn(p3));
            }
#pragma unroll
            for (int nt = 0; nt < 8; nt++) {
                oacc[mt][nt][0] *= aL; oacc[mt][nt][1] *= aL;
                oacc[mt][nt][2] *= aH; oacc[mt][nt][3] *= aH;
            }
            lsL += __shfl_xor_sync(0xFFFFFFFFu, lsL, 1);
            lsL += __shfl_xor_sync(0xFFFFFFFFu, lsL, 2);
            lsH += __shfl_xor_sync(0xFFFFFFFFu, lsH, 1);
            lsH += __shfl_xor_sync(0xFFFFFFFFu, lsH, 2);
            if (t4 == 0) {
                plsum[nh * 128 + rL] = lsL;
                plsum[nh * 128 + rH] = lsH;
            }
        }
        __syncthreads();

        // ---- m/l update (runs concurrent with PV; no conflicts) ----
        if (tid < 128) {
            float mo = mrow[tid];
            float mn = fmaxf(mo, fmaxf(pmax[tid], pmax[128 + tid]));
            lrow[tid] = lrow[tid] * __expf(mo - mn) + plsum[tid] + plsum[128 + tid];
            mrow[tid] = mn;
        }

        // ---- O += P @ V (single fp16) ----
#pragma unroll
        for (int ks = 0; ks < 4; ks++) {
            uint32_t pa[2][4];
#pragma unroll
            for (int mt = 0; mt < 2; mt++) {
                const __half* p = Pp + (m0 + mt * 16 + g) * ALDV + ks * 16 + t4 * 2;
                pa[mt][0] = ld32(p);
                pa[mt][1] = ld32(p + 8 * ALDV);
                pa[mt][2] = ld32(p + 8);
                pa[mt][3] = ld32(p + 8 * ALDV + 8);
            }
#pragma unroll
            for (int nt = 0; nt < 8; nt++) {
                const __half* pb = Vt + (nh * 64 + nt * 8 + g) * ALDV + ks * 16 + t4 * 2;
                uint32_t b2[2] = {ld32(pb), ld32(pb + 8)};
                mma16(oacc[0][nt], pa[0], b2);
                mma16(oacc[1][nt], pa[1], b2);
            }
        }
    }
    __syncthreads();

    // ---- epilogue: normalize, split fp16 hi/lo, store AO [s][hid] ----
#pragma unroll
    for (int mt = 0; mt < 2; mt++) {
        int rL = m0 + mt * 16 + g, rH = rL + 8;
        float invL = 1.f / lrow[rL], invH = 1.f / lrow[rH];
        size_t sL = (size_t)(rb * 128 + rL) * HIDDEN;
        size_t sH = (size_t)(rb * 128 + rH) * HIDDEN;
#pragma unroll
        for (int nt = 0; nt < 8; nt++) {
            int col = hq * HD + nh * 64 + nt * 8 + 2 * t4;
            __half h0, l0, h1, l1;
            split16(oacc[mt][nt][0] * invL, h0, l0);
            split16(oacc[mt][nt][1] * invL, h1, l1);
            *(__half2*)&AOh[sL + col] = __halves2half2(h0, h1);
            *(__half2*)&AOl[sL + col] = __halves2half2(l0, l1);
            split16(oacc[mt][nt][2] * invH, h0, l0);
            split16(oacc[mt][nt][3] * invH, h1, l1);
            *(__half2*)&AOh[sH + col] = __halves2half2(h0, h1);
            *(__half2*)&AOl[sH + col] = __halves2half2(l0, l1);
        }
    }
}

// ---------------------------------------------------------------------------
extern "C" void kernel_launch(void* const* d_in, const int* in_sizes, int n_in,
                              void* d_out, int out_size)
{
    const float* hs   = (const float*)d_in[0];
    const float* cosT = (const float*)d_in[1];
    const float* sinT = (const float*)d_in[2];
    // d_in[3] = attention_mask: pure causal, implemented directly (not read)
    const float* Wq = (const float*)d_in[4];
    const float* Wk = (const float*)d_in[5];
    const float* Wv = (const float*)d_in[6];
    const float* Wo = (const float*)d_in[7];
    const float* qw = (const float*)d_in[8];
    const float* kw = (const float*)d_in[9];
    float* out = (float*)d_out;

    float *qraw, *kraw, *vraw;
    __half *hsH, *hsL, *wqH, *wqL, *wkH, *wkL, *wvH, *wvL, *woH, *woL;
    __half *qnH, *qnL, *knH, *knL, *vnT, *aoH, *aoL;
    cudaGetSymbolAddress((void**)&qraw, g_Qraw);
    cudaGetSymbolAddress((void**)&kraw, g_Kraw);
    cudaGetSymbolAddress((void**)&vraw, g_Vraw);
    cudaGetSymbolAddress((void**)&hsH, g_hsH); cudaGetSymbolAddress((void**)&hsL, g_hsL);
    cudaGetSymbolAddress((void**)&wqH, g_WqH); cudaGetSymbolAddress((void**)&wqL, g_WqL);
    cudaGetSymbolAddress((void**)&wkH, g_WkH); cudaGetSymbolAddress((void**)&wkL, g_WkL);
    cudaGetSymbolAddress((void**)&wvH, g_WvH); cudaGetSymbolAddress((void**)&wvL, g_WvL);
    cudaGetSymbolAddress((void**)&woH, g_WoH); cudaGetSymbolAddress((void**)&woL, g_WoL);
    cudaGetSymbolAddress((void**)&qnH, g_QnH); cudaGetSymbolAddress((void**)&qnL, g_QnL);
    cudaGetSymbolAddress((void**)&knH, g_KnH); cudaGetSymbolAddress((void**)&knL, g_KnL);
    cudaGetSymbolAddress((void**)&vnT, g_VnT);
    cudaGetSymbolAddress((void**)&aoH, g_AOH); cudaGetSymbolAddress((void**)&aoL, g_AOL);

    cudaFuncSetAttribute(gemm_fp16x3,
                         cudaFuncAttributeMaxDynamicSharedMemorySize, GEMM_SMEM_BYTES);
    cudaFuncSetAttribute(attn_fp16_kernel,
                         cudaFuncAttributeMaxDynamicSharedMemorySize, ATTN_SMEM_BYTES);

    // split inputs to fp16 hi/lo
    split_kernel<<<(S_LEN * HIDDEN / 4 + 255) / 256, 256>>>(hs, hsH, hsL, S_LEN * HIDDEN / 4);
    split_kernel<<<(HIDDEN * HIDDEN / 4 + 255) / 256, 256>>>(Wq, wqH, wqL, HIDDEN * HIDDEN / 4);
    split_kernel<<<(NKV * HD * HIDDEN / 4 + 255) / 256, 256>>>(Wk, wkH, wkL, NKV * HD * HIDDEN / 4);
    split_kernel<<<(NKV * HD * HIDDEN / 4 + 255) / 256, 256>>>(Wv, wvH, wvL, NKV * HD * HIDDEN / 4);
    split_kernel<<<(HIDDEN * HIDDEN / 4 + 255) / 256, 256>>>(Wo, woH, woL, HIDDEN * HIDDEN / 4);

    // QKV projections
    gemm_fp16x3<<<dim3(HIDDEN / 128, S_LEN / 128), 256, GEMM_SMEM_BYTES>>>(
        hsH, hsL, wqH, wqL, qraw, S_LEN, HIDDEN, HIDDEN);
    gemm_fp16x3<<<dim3(NKV * HD / 128, S_LEN / 128), 256, GEMM_SMEM_BYTES>>>(
        hsH, hsL, wkH, wkL, kraw, S_LEN, NKV * HD, HIDDEN);
    gemm_fp16x3<<<dim3(NKV * HD / 128, S_LEN / 128), 256, GEMM_SMEM_BYTES>>>(
        hsH, hsL, wvH, wvL, vraw, S_LEN, NKV * HD, HIDDEN);

    // RMSNorm (+RoPE), emit fp16 hi/lo (Q,K) and transposed fp16 (V)
    norm_rope_fp16<<<(S_LEN * NH + 3) / 4, 128>>>(qraw, qnH, qnL, qw, cosT, sinT, NH, 1);
    norm_rope_fp16<<<(S_LEN * NKV + 3) / 4, 128>>>(kraw, knH, knL, kw, cosT, sinT, NKV, 1);
    norm_rope_fp16<<<(S_LEN * NKV + 3) / 4, 128>>>(vraw, vnT, nullptr, nullptr, cosT, sinT, NKV, 0);

    // attention
    attn_fp16_kernel<<<dim3(S_LEN / 128, NH), 256, ATTN_SMEM_BYTES>>>(
        qnH, qnL, knH, knL, vnT, aoH, aoL);

    // output projection
    gemm_fp16x3<<<dim3(HIDDEN / 128, S_LEN / 128), 256, GEMM_SMEM_BYTES>>>(
        aoH, aoL, woH, woL, out, S_LEN, HIDDEN, HIDDEN);
}

// round 5
// speedup vs baseline: 3.7543x; 1.1012x over previous
#include <cuda_runtime.h>
#include <cuda_fp16.h>
#include <math.h>
#include <stdint.h>

#define S_LEN 4096
#define HIDDEN 2048
#define NH 16
#define NKV 4
#define HD 128

// ---------------- device-global scratch (no runtime alloc allowed) ----------
__device__ float g_Qraw[S_LEN * HIDDEN];
__device__ float g_Kraw[S_LEN * NKV * HD];
__device__ float g_Vraw[S_LEN * NKV * HD];

__device__ __half g_hsH[S_LEN * HIDDEN],   g_hsL[S_LEN * HIDDEN];
__device__ __half g_WqH[HIDDEN * HIDDEN],  g_WqL[HIDDEN * HIDDEN];
__device__ __half g_WkH[NKV * HD * HIDDEN], g_WkL[NKV * HD * HIDDEN];
__device__ __half g_WvH[NKV * HD * HIDDEN], g_WvL[NKV * HD * HIDDEN];
__device__ __half g_WoH[HIDDEN * HIDDEN],  g_WoL[HIDDEN * HIDDEN];

__device__ __half g_QnH[NH * S_LEN * HD],  g_QnL[NH * S_LEN * HD];   // [h][s][d]
__device__ __half g_KnH[NKV * S_LEN * HD], g_KnL[NKV * S_LEN * HD];  // [kv][s][d]
__device__ __half g_VnT[NKV * HD * S_LEN];                           // [kv][d][s]
__device__ __half g_AOH[S_LEN * HIDDEN],   g_AOL[S_LEN * HIDDEN];    // [s][hid]

// ---------------- helpers ---------------------------------------------------
__device__ __forceinline__ void split16(float x, __half& hi, __half& lo) {
    hi = __float2half_rn(x);
    lo = __float2half_rn(x - __half2float(hi));
}
__device__ __forceinline__ void cp16(uint32_t dst, const void* src) {
    asm volatile("cp.async.cg.shared.global [%0], [%1], 16;\n" :: "r"(dst), "l"(src));
}
__device__ __forceinline__ void cp_commit() {
    asm volatile("cp.async.commit_group;\n");
}
template <int N>
__device__ __forceinline__ void cp_wait() {
    asm volatile("cp.async.wait_group %0;\n" :: "n"(N));
}
// ldmatrix x4: r[0..3] = four 8x8 b16 tiles; lane l supplies row address of
// tile (l>>3), row (l&7). Result per tile: lane l holds (row l>>2, col 2(l&3)).
__device__ __forceinline__ void ldsm4(uint32_t* r, uint32_t a) {
    asm volatile("ldmatrix.sync.aligned.m8n8.x4.shared.b16 {%0,%1,%2,%3}, [%4];\n"
                 : "=r"(r[0]), "=r"(r[1]), "=r"(r[2]), "=r"(r[3]) : "r"(a));
}
// fp16 m16n8k16, fp32 accum.
__device__ __forceinline__ void mma16(float* c, const uint32_t* a, const uint32_t* b) {
    asm volatile(
        "mma.sync.aligned.m16n8k16.row.col.f32.f16.f16.f32 "
        "{%0,%1,%2,%3},{%4,%5,%6,%7},{%8,%9},{%0,%1,%2,%3};\n"
        : "+f"(c[0]), "+f"(c[1]), "+f"(c[2]), "+f"(c[3])
        : "r"(a[0]), "r"(a[1]), "r"(a[2]), "r"(a[3]), "r"(b[0]), "r"(b[1]));
}

// ---------------- fused fp32 -> fp16 hi/lo split (5 tensors, 1 launch) ------
struct SplitJob { const float* in; __half* hi; __half* lo; int n4; };

__global__ void __launch_bounds__(256) split_all_kernel(
    SplitJob j0, SplitJob j1, SplitJob j2, SplitJob j3, SplitJob j4)
{
    int i = blockIdx.x * 256 + threadIdx.x;
    const float* in; __half *hi, *lo;
    if (i < j0.n4)      { in = j0.in; hi = j0.hi; lo = j0.lo; }
    else if ((i -= j0.n4) < j1.n4) { in = j1.in; hi = j1.hi; lo = j1.lo; }
    else if ((i -= j1.n4) < j2.n4) { in = j2.in; hi = j2.hi; lo = j2.lo; }
    else if ((i -= j2.n4) < j3.n4) { in = j3.in; hi = j3.hi; lo = j3.lo; }
    else if ((i -= j3.n4) < j4.n4) { in = j4.in; hi = j4.hi; lo = j4.lo; }
    else return;
    float4 v = ((const float4*)in)[i];
    __half h0, l0, h1, l1, h2, l2, h3, l3;
    split16(v.x, h0, l0); split16(v.y, h1, l1);
    split16(v.z, h2, l2); split16(v.w, h3, l3);
    ((__half2*)hi)[2 * i]     = __halves2half2(h0, h1);
    ((__half2*)hi)[2 * i + 1] = __halves2half2(h2, h3);
    ((__half2*)lo)[2 * i]     = __halves2half2(l0, l1);
    ((__half2*)lo)[2 * i + 1] = __halves2half2(l2, l3);
}

// ---------------- fp16x3 GEMM: C[M,N] = A[M,K] @ B[N,K]^T -------------------
// 128x128 block, 256 thr (8 warps, 32x64 warp tiles), k-chunk 32, 3-stage
// cp.async pipeline, ldmatrix fragment loads.
#define GK 32
#define GLDH 40                       // halves per smem row (32 + 8 pad)
#define GST 3
#define GARR (128 * GLDH)             // halves per array per stage
#define GSTAGE (4 * GARR)             // Ah, Al, Bh, Bl
#define GEMM_SMEM_BYTES (GST * GSTAGE * 2)

__global__ void __launch_bounds__(256) gemm_fp16x3(
    const __half* __restrict__ Ah, const __half* __restrict__ Al,
    const __half* __restrict__ Bh, const __half* __restrict__ Bl,
    float* __restrict__ C, int M, int N, int K)
{
    extern __shared__ __half smh[];
    uint32_t sbase = (uint32_t)__cvta_generic_to_shared(smh);
    const int tid = threadIdx.x, w = tid >> 5, lane = tid & 31;
    const int g = lane >> 2, t4 = lane & 3;
    const int wm = w >> 1, wn = w & 1;
    const int la7 = lane & 7, lb = (lane >> 3) & 1, lc = (lane >> 4) & 1;
    // ldmatrix per-lane byte offsets (within each array)
    const uint32_t offA = ((uint32_t)(wm * 32 + la7 + lb * 8) * GLDH + lc * 8) * 2;
    const uint32_t offB = ((uint32_t)(wn * 64 + lc * 8 + la7) * GLDH + lb * 8) * 2;

    const __half* A0h = Ah + (size_t)blockIdx.y * 128 * K;
    const __half* A0l = Al + (size_t)blockIdx.y * 128 * K;
    const __half* B0h = Bh + (size_t)blockIdx.x * 128 * K;
    const __half* B0l = Bl + (size_t)blockIdx.x * 128 * K;
    const int nch = K / GK;

    float acc[2][8][4];
#pragma unroll
    for (int mt = 0; mt < 2; mt++)
#pragma unroll
        for (int nt = 0; nt < 8; nt++)
#pragma unroll
            for (int r = 0; r < 4; r++) acc[mt][nt][r] = 0.f;

    auto issue = [&](int chunk) {
        int st = chunk % GST;
        uint32_t sb = sbase + (uint32_t)(st * GSTAGE * 2);
        int k0 = chunk * GK;
#pragma unroll
        for (int j = 0; j < 2; j++) {
            int c = tid + j * 256;            // 0..511
            int row = c >> 2, seg = c & 3;    // seg: 16B chunk (8 halves)
            size_t go = (size_t)row * K + k0 + seg * 8;
            uint32_t so = (uint32_t)(row * GLDH + seg * 8) * 2;
            cp16(sb + 0 * GARR * 2 + so, A0h + go);
            cp16(sb + 1 * GARR * 2 + so, A0l + go);
            cp16(sb + 2 * GARR * 2 + so, B0h + go);
            cp16(sb + 3 * GARR * 2 + so, B0l + go);
        }
    };

    issue(0); cp_commit();
    issue(1); cp_commit();

    for (int i = 0; i < nch; i++) {
        if (i + 2 < nch) issue(i + 2);
        cp_commit();
        cp_wait<2>();
        __syncthreads();
        uint32_t base = sbase + (uint32_t)((i % GST) * GSTAGE * 2);
#pragma unroll
        for (int ks = 0; ks < 2; ks++) {
            uint32_t ah[2][4], al[2][4];
#pragma unroll
            for (int mt = 0; mt < 2; mt++) {
                uint32_t o = offA + (uint32_t)(mt * 16 * GLDH + ks * 16) * 2;
                ldsm4(ah[mt], base + o);
                ldsm4(al[mt], base + GARR * 2 + o);
            }
            uint32_t bh[4][4], bl[4][4];
#pragma unroll
            for (int p = 0; p < 4; p++) {
                uint32_t o = offB + (uint32_t)(p * 16 * GLDH + ks * 16) * 2;
                ldsm4(bh[p], base + 2 * GARR * 2 + o);
                ldsm4(bl[p], base + 3 * GARR * 2 + o);
            }
#pragma unroll
            for (int nt = 0; nt < 8; nt++) {
                uint32_t bh2[2] = {bh[nt >> 1][(nt & 1) * 2], bh[nt >> 1][(nt & 1) * 2 + 1]};
                uint32_t bl2[2] = {bl[nt >> 1][(nt & 1) * 2], bl[nt >> 1][(nt & 1) * 2 + 1]};
                mma16(acc[0][nt], ah[0], bh2);
                mma16(acc[1][nt], ah[1], bh2);
                mma16(acc[0][nt], ah[0], bl2);
                mma16(acc[1][nt], ah[1], bl2);
                mma16(acc[0][nt], al[0], bh2);
                mma16(acc[1][nt], al[1], bh2);
            }
        }
        __syncthreads();
    }

#pragma unroll
    for (int mt = 0; mt < 2; mt++) {
        int r0 = blockIdx.y * 128 + wm * 32 + mt * 16 + g;
#pragma unroll
        for (int nt = 0; nt < 8; nt++) {
            int col = blockIdx.x * 128 + wn * 64 + nt * 8 + 2 * t4;
            *(float2*)&C[(size_t)r0 * N + col] =
                make_float2(acc[mt][nt][0], acc[mt][nt][1]);
            *(float2*)&C[(size_t)(r0 + 8) * N + col] =
                make_float2(acc[mt][nt][2], acc[mt][nt][3]);
        }
    }
}

// ---------------- RMSNorm (+RoPE) -> fp16 outputs ---------------------------
__global__ void __launch_bounds__(128) norm_rope_fp16(
    const float* __restrict__ in, __half* __restrict__ outH,
    __half* __restrict__ outL, const float* __restrict__ w,
    const float* __restrict__ cosT, const float* __restrict__ sinT,
    int nheads, int mode)
{
    int task = blockIdx.x * 4 + (threadIdx.x >> 5);
    int lane = threadIdx.x & 31;
    if (task >= S_LEN * nheads) return;
    int s = task / nheads, hh = task - s * nheads;

    const float* x = in + (size_t)s * (nheads * HD) + hh * HD;
    float v0 = x[lane], v1 = x[lane + 32], v2 = x[lane + 64], v3 = x[lane + 96];
    float ss = v0 * v0 + v1 * v1 + v2 * v2 + v3 * v3;
#pragma unroll
    for (int o = 16; o > 0; o >>= 1) ss += __shfl_xor_sync(0xFFFFFFFFu, ss, o);
    float inv = rsqrtf(ss * (1.f / HD) + 1e-6f);
    float n0 = v0 * inv, n1 = v1 * inv, n2 = v2 * inv, n3 = v3 * inv;

    if (mode) {
        n0 *= w[lane]; n1 *= w[lane + 32]; n2 *= w[lane + 64]; n3 *= w[lane + 96];
        const float* c  = cosT + (size_t)s * HD;
        const float* sn = sinT + (size_t)s * HD;
        float o0 = n0 * c[lane]      - n2 * sn[lane];
        float o1 = n1 * c[lane + 32] - n3 * sn[lane + 32];
        float o2 = n2 * c[lane + 64] + n0 * sn[lane + 64];
        float o3 = n3 * c[lane + 96] + n1 * sn[lane + 96];
        __half ah, al;
        __half* yh = outH + ((size_t)hh * S_LEN + s) * HD;
        __half* yl = outL + ((size_t)hh * S_LEN + s) * HD;
        split16(o0, ah, al); yh[lane] = ah;      yl[lane] = al;
        split16(o1, ah, al); yh[lane + 32] = ah; yl[lane + 32] = al;
        split16(o2, ah, al); yh[lane + 64] = ah; yl[lane + 64] = al;
        split16(o3, ah, al); yh[lane + 96] = ah; yl[lane + 96] = al;
    } else {
        __half* y = outH + (size_t)hh * HD * S_LEN;
        y[(size_t)(lane)      * S_LEN + s] = __float2half_rn(n0);
        y[(size_t)(lane + 32) * S_LEN + s] = __float2half_rn(n1);
        y[(size_t)(lane + 64) * S_LEN + s] = __float2half_rn(n2);
        y[(size_t)(lane + 96) * S_LEN + s] = __float2half_rn(n3);
    }
}

// ---------------- causal GQA flash attention, fp16 MMA ----------------------
// Block: 128 q-rows x head (head-major grid, heavy rb first). 256 thr.
// QK^T fp16x3, PV single fp16; cp.async double-buffered K/V; ldmatrix frags.
#define ALDQ 136
#define ALDV 72
#define OFF_QH 0
#define OFF_QL (128 * ALDQ)
#define OFF_KH0 (2 * 128 * ALDQ)
#define OFF_KL0 (OFF_KH0 + 64 * ALDQ)
#define OFF_KH1 (OFF_KL0 + 64 * ALDQ)
#define OFF_KL1 (OFF_KH1 + 64 * ALDQ)
#define OFF_VT0 (OFF_KL1 + 64 * ALDQ)
#define OFF_VT1 (OFF_VT0 + 128 * ALDV)
#define OFF_PP  (OFF_VT1 + 128 * ALDV)
#define HALVES_TOT (OFF_PP + 128 * ALDV)
#define ATTN_SMEM_BYTES (HALVES_TOT * 2 + (2 * 128 + 2 * 128 + 128 + 128) * 4)

__global__ void __launch_bounds__(256) attn_fp16_kernel(
    const __half* __restrict__ Qh_g, const __half* __restrict__ Ql_g,
    const __half* __restrict__ Kh_g, const __half* __restrict__ Kl_g,
    const __half* __restrict__ Vt_g,
    __half* __restrict__ AOh, __half* __restrict__ AOl)
{
    extern __shared__ __half sm[];
    __half* Qh = sm + OFF_QH;
    __half* Ql = sm + OFF_QL;
    __half* Pp = sm + OFF_PP;
    float* pmax  = (float*)(sm + HALVES_TOT);     // [2][128]
    float* plsum = pmax + 2 * 128;                // [2][128]
    float* mrow  = plsum + 2 * 128;               // [128]
    float* lrow  = mrow + 128;                    // [128]
    uint32_t su = (uint32_t)__cvta_generic_to_shared(sm);
    const uint32_t uKH[2] = {su + OFF_KH0 * 2, su + OFF_KH1 * 2};
    const uint32_t uKL[2] = {su + OFF_KL0 * 2, su + OFF_KL1 * 2};
    const uint32_t uVT[2] = {su + OFF_VT0 * 2, su + OFF_VT1 * 2};

    const int hq = blockIdx.x;
    const int rb = (gridDim.y - 1) - blockIdx.y;   // heavy blocks launch first
    const int kvh = hq >> 2;
    const int tid = threadIdx.x, w = tid >> 5, lane = tid & 31;
    const int g = lane >> 2, t4 = lane & 3;
    const int m0 = (w >> 1) * 32;   // 32-row strip
    const int nh = w & 1;           // column half
    const int la7 = lane & 7, lb = (lane >> 3) & 1, lc = (lane >> 4) & 1;

    // ldmatrix per-lane byte offsets
    const uint32_t offQA = ((uint32_t)(m0 + la7 + lb * 8) * ALDQ + lc * 8) * 2;
    const uint32_t offKB = ((uint32_t)(nh * 32 + lc * 8 + la7) * ALDQ + lb * 8) * 2;
    const uint32_t offPA = ((uint32_t)(m0 + la7 + lb * 8) * ALDV + lc * 8) * 2;
    const uint32_t offVB = ((uint32_t)(nh * 64 + lc * 8 + la7) * ALDV + lb * 8) * 2;

    const __half* Qg_h = Qh_g + ((size_t)hq * S_LEN + rb * 128) * HD;
    const __half* Qg_l = Ql_g + ((size_t)hq * S_LEN + rb * 128) * HD;
    const __half* Kg_h = Kh_g + (size_t)kvh * S_LEN * HD;
    const __half* Kg_l = Kl_g + (size_t)kvh * S_LEN * HD;
    const __half* Vg   = Vt_g + (size_t)kvh * HD * S_LEN;

    auto issueKV = [&](int kb) {
        int st = kb & 1;
#pragma unroll
        for (int j = 0; j < 4; j++) {
            int c = tid + j * 256;            // 0..1023
            int row = c >> 4, seg = c & 15;
            size_t go = (size_t)(kb * 64 + row) * HD + seg * 8;
            uint32_t so = (uint32_t)(row * ALDQ + seg * 8) * 2;
            cp16(uKH[st] + so, Kg_h + go);
            cp16(uKL[st] + so, Kg_l + go);
            int vrow = c >> 3, vseg = c & 7;
            cp16(uVT[st] + (uint32_t)(vrow * ALDV + vseg * 8) * 2,
                 Vg + (size_t)vrow * S_LEN + kb * 64 + vseg * 8);
        }
    };

    issueKV(0); cp_commit();

    // Q tiles (hi/lo), plain loads (overlap with the cp.async above)
#pragma unroll
    for (int j = 0; j < 8; j++) {
        int c = tid + j * 256;            // 0..2047
        int row = c >> 4, seg = c & 15;
        *(uint4*)&Qh[row * ALDQ + seg * 8] =
            *(const uint4*)(Qg_h + (size_t)row * HD + seg * 8);
        *(uint4*)&Ql[row * ALDQ + seg * 8] =
            *(const uint4*)(Qg_l + (size_t)row * HD + seg * 8);
    }
    if (tid < 128) { mrow[tid] = -INFINITY; lrow[tid] = 0.f; }

    float oacc[2][8][4];
#pragma unroll
    for (int mt = 0; mt < 2; mt++)
#pragma unroll
        for (int nt = 0; nt < 8; nt++)
#pragma unroll
            for (int r = 0; r < 4; r++) oacc[mt][nt][r] = 0.f;

    const int kbmax = 2 * rb + 1;
    for (int kb = 0; kb <= kbmax; kb++) {
        const int st = kb & 1;
        cp_wait<0>();
        __syncthreads();   // tile kb resident AND all threads done with kb-1
        if (kb + 1 <= kbmax) { issueKV(kb + 1); cp_commit(); }

        // ---- S = Q K^T (fp16x3) ----
        float sacc[2][4][4];
#pragma unroll
        for (int mt = 0; mt < 2; mt++)
#pragma unroll
            for (int nt = 0; nt < 4; nt++)
#pragma unroll
                for (int r = 0; r < 4; r++) sacc[mt][nt][r] = 0.f;

#pragma unroll
        for (int ks = 0; ks < 8; ks++) {
            uint32_t ah[2][4], al[2][4];
#pragma unroll
            for (int mt = 0; mt < 2; mt++) {
                uint32_t o = offQA + (uint32_t)(mt * 16 * ALDQ + ks * 16) * 2;
                ldsm4(ah[mt], su + OFF_QH * 2 + o);
                ldsm4(al[mt], su + OFF_QL * 2 + o);
            }
            uint32_t bh[2][4], bl[2][4];
#pragma unroll
            for (int p = 0; p < 2; p++) {
                uint32_t o = offKB + (uint32_t)(p * 16 * ALDQ + ks * 16) * 2;
                ldsm4(bh[p], uKH[st] + o);
                ldsm4(bl[p], uKL[st] + o);
            }
#pragma unroll
            for (int nt = 0; nt < 4; nt++) {
                uint32_t bh2[2] = {bh[nt >> 1][(nt & 1) * 2], bh[nt >> 1][(nt & 1) * 2 + 1]};
                uint32_t bl2[2] = {bl[nt >> 1][(nt & 1) * 2], bl[nt >> 1][(nt & 1) * 2 + 1]};
                mma16(sacc[0][nt], ah[0], bh2);
                mma16(sacc[1][nt], ah[1], bh2);
                mma16(sacc[0][nt], ah[0], bl2);
                mma16(sacc[1][nt], ah[1], bl2);
                mma16(sacc[0][nt], al[0], bh2);
                mma16(sacc[1][nt], al[1], bh2);
            }
        }

        // ---- causal mask (register-level) ----
        if (kb >= 2 * rb) {
#pragma unroll
            for (int mt = 0; mt < 2; mt++) {
                int r0 = rb * 128 + m0 + mt * 16 + g;
                int r1 = r0 + 8;
#pragma unroll
                for (int nt = 0; nt < 4; nt++) {
                    int c0 = kb * 64 + nh * 32 + nt * 8 + 2 * t4;
                    if (c0 > r0)     sacc[mt][nt][0] = -INFINITY;
                    if (c0 + 1 > r0) sacc[mt][nt][1] = -INFINITY;
                    if (c0 > r1)     sacc[mt][nt][2] = -INFINITY;
                    if (c0 + 1 > r1) sacc[mt][nt][3] = -INFINITY;
                }
            }
        }

        // ---- per-warp row max -> pmax[nh][row] ----
#pragma unroll
        for (int mt = 0; mt < 2; mt++) {
            float rmL = -INFINITY, rmH = -INFINITY;
#pragma unroll
            for (int nt = 0; nt < 4; nt++) {
                rmL = fmaxf(rmL, fmaxf(sacc[mt][nt][0], sacc[mt][nt][1]));
                rmH = fmaxf(rmH, fmaxf(sacc[mt][nt][2], sacc[mt][nt][3]));
            }
            rmL = fmaxf(rmL, __shfl_xor_sync(0xFFFFFFFFu, rmL, 1));
            rmL = fmaxf(rmL, __shfl_xor_sync(0xFFFFFFFFu, rmL, 2));
            rmH = fmaxf(rmH, __shfl_xor_sync(0xFFFFFFFFu, rmH, 1));
            rmH = fmaxf(rmH, __shfl_xor_sync(0xFFFFFFFFu, rmH, 2));
            if (t4 == 0) {
                pmax[nh * 128 + m0 + mt * 16 + g]     = rmL;
                pmax[nh * 128 + m0 + mt * 16 + g + 8] = rmH;
            }
        }
        __syncthreads();

        // ---- p = exp(s-mnew); rescale oacc; Pp fp16; lsum partials ----
#pragma unroll
        for (int mt = 0; mt < 2; mt++) {
            int rL = m0 + mt * 16 + g, rH = rL + 8;
            float moL = mrow[rL];
            float mnL = fmaxf(moL, fmaxf(pmax[rL], pmax[128 + rL]));
            float aL  = __expf(moL - mnL);
            float moH = mrow[rH];
            float mnH = fmaxf(moH, fmaxf(pmax[rH], pmax[128 + rH]));
            float aH  = __expf(moH - mnH);
            float lsL = 0.f, lsH = 0.f;
#pragma unroll
            for (int nt = 0; nt < 4; nt++) {
                float p0 = __expf(sacc[mt][nt][0] - mnL);
                float p1 = __expf(sacc[mt][nt][1] - mnL);
                float p2 = __expf(sacc[mt][nt][2] - mnH);
                float p3 = __expf(sacc[mt][nt][3] - mnH);
                lsL += p0 + p1; lsH += p2 + p3;
                int ct = nh * 32 + nt * 8 + 2 * t4;
                *(__half2*)&Pp[rL * ALDV + ct] =
                    __halves2half2(__float2half_rn(p0), __float2half_rn(p1));
                *(__half2*)&Pp[rH * ALDV + ct] =
                    __halves2half2(__float2half_rn(p2), __float2half_rn(p3));
            }
#pragma unroll
            for (int nt = 0; nt < 8; nt++) {
                oacc[mt][nt][0] *= aL; oacc[mt][nt][1] *= aL;
                oacc[mt][nt][2] *= aH; oacc[mt][nt][3] *= aH;
            }
            lsL += __shfl_xor_sync(0xFFFFFFFFu, lsL, 1);
            lsL += __shfl_xor_sync(0xFFFFFFFFu, lsL, 2);
            lsH += __shfl_xor_sync(0xFFFFFFFFu, lsH, 1);
            lsH += __shfl_xor_sync(0xFFFFFFFFu, lsH, 2);
            if (t4 == 0) {
                plsum[nh * 128 + rL] = lsL;
                plsum[nh * 128 + rH] = lsH;
            }
        }
        __syncthreads();

        // ---- m/l update (concurrent with PV; no conflicts) ----
        if (tid < 128) {
            float mo = mrow[tid];
            float mn = fmaxf(mo, fmaxf(pmax[tid], pmax[128 + tid]));
            lrow[tid] = lrow[tid] * __expf(mo - mn) + plsum[tid] + plsum[128 + tid];
            mrow[tid] = mn;
        }

        // ---- O += P @ V (single fp16) ----
#pragma unroll
        for (int ks = 0; ks < 4; ks++) {
            uint32_t pa[2][4];
#pragma unroll
            for (int mt = 0; mt < 2; mt++) {
                uint32_t o = offPA + (uint32_t)(mt * 16 * ALDV + ks * 16) * 2;
                ldsm4(pa[mt], su + OFF_PP * 2 + o);
            }
            uint32_t vb[4][4];
#pragma unroll
            for (int p = 0; p < 4; p++) {
                uint32_t o = offVB + (uint32_t)(p * 16 * ALDV + ks * 16) * 2;
                ldsm4(vb[p], uVT[st] + o);
            }
#pragma unroll
            for (int nt = 0; nt < 8; nt++) {
                uint32_t b2[2] = {vb[nt >> 1][(nt & 1) * 2], vb[nt >> 1][(nt & 1) * 2 + 1]};
                mma16(oacc[0][nt], pa[0], b2);
                mma16(oacc[1][nt], pa[1], b2);
            }
        }
    }
    __syncthreads();

    // ---- epilogue: normalize, split fp16 hi/lo, store AO [s][hid] ----
#pragma unroll
    for (int mt = 0; mt < 2; mt++) {
        int rL = m0 + mt * 16 + g, rH = rL + 8;
        float invL = 1.f / lrow[rL], invH = 1.f / lrow[rH];
        size_t sL = (size_t)(rb * 128 + rL) * HIDDEN;
        size_t sH = (size_t)(rb * 128 + rH) * HIDDEN;
#pragma unroll
        for (int nt = 0; nt < 8; nt++) {
            int col = hq * HD + nh * 64 + nt * 8 + 2 * t4;
            __half h0, l0, h1, l1;
            split16(oacc[mt][nt][0] * invL, h0, l0);
            split16(oacc[mt][nt][1] * invL, h1, l1);
            *(__half2*)&AOh[sL + col] = __halves2half2(h0, h1);
            *(__half2*)&AOl[sL + col] = __halves2half2(l0, l1);
            split16(oacc[mt][nt][2] * invH, h0, l0);
            split16(oacc[mt][nt][3] * invH, h1, l1);
            *(__half2*)&AOh[sH + col] = __halves2half2(h0, h1);
            *(__half2*)&AOl[sH + col] = __halves2half2(l0, l1);
        }
    }
}

// ---------------------------------------------------------------------------
extern "C" void kernel_launch(void* const* d_in, const int* in_sizes, int n_in,
                              void* d_out, int out_size)
{
    const float* hs   = (const float*)d_in[0];
    const float* cosT = (const float*)d_in[1];
    const float* sinT = (const float*)d_in[2];
    // d_in[3] = attention_mask: pure causal, implemented directly (not read)
    const float* Wq = (const float*)d_in[4];
    const float* Wk = (const float*)d_in[5];
    const float* Wv = (const float*)d_in[6];
    const float* Wo = (const float*)d_in[7];
    const float* qw = (const float*)d_in[8];
    const float* kw = (const float*)d_in[9];
    float* out = (float*)d_out;

    float *qraw, *kraw, *vraw;
    __half *hsH, *hsL, *wqH, *wqL, *wkH, *wkL, *wvH, *wvL, *woH, *woL;
    __half *qnH, *qnL, *knH, *knL, *vnT, *aoH, *aoL;
    cudaGetSymbolAddress((void**)&qraw, g_Qraw);
    cudaGetSymbolAddress((void**)&kraw, g_Kraw);
    cudaGetSymbolAddress((void**)&vraw, g_Vraw);
    cudaGetSymbolAddress((void**)&hsH, g_hsH); cudaGetSymbolAddress((void**)&hsL, g_hsL);
    cudaGetSymbolAddress((void**)&wqH, g_WqH); cudaGetSymbolAddress((void**)&wqL, g_WqL);
    cudaGetSymbolAddress((void**)&wkH, g_WkH); cudaGetSymbolAddress((void**)&wkL, g_WkL);
    cudaGetSymbolAddress((void**)&wvH, g_WvH); cudaGetSymbolAddress((void**)&wvL, g_WvL);
    cudaGetSymbolAddress((void**)&woH, g_WoH); cudaGetSymbolAddress((void**)&woL, g_WoL);
    cudaGetSymbolAddress((void**)&qnH, g_QnH); cudaGetSymbolAddress((void**)&qnL, g_QnL);
    cudaGetSymbolAddress((void**)&knH, g_KnH); cudaGetSymbolAddress((void**)&knL, g_KnL);
    cudaGetSymbolAddress((void**)&vnT, g_VnT);
    cudaGetSymbolAddress((void**)&aoH, g_AOH); cudaGetSymbolAddress((void**)&aoL, g_AOL);

    cudaFuncSetAttribute(gemm_fp16x3,
                         cudaFuncAttributeMaxDynamicSharedMemorySize, GEMM_SMEM_BYTES);
    cudaFuncSetAttribute(attn_fp16_kernel,
                         cudaFuncAttributeMaxDynamicSharedMemorySize, ATTN_SMEM_BYTES);

    // split inputs to fp16 hi/lo (single fused launch)
    {
        SplitJob j0 = {hs, hsH, hsL, S_LEN * HIDDEN / 4};
        SplitJob j1 = {Wq, wqH, wqL, HIDDEN * HIDDEN / 4};
        SplitJob j2 = {Wk, wkH, wkL, NKV * HD * HIDDEN / 4};
        SplitJob j3 = {Wv, wvH, wvL, NKV * HD * HIDDEN / 4};
        SplitJob j4 = {Wo, woH, woL, HIDDEN * HIDDEN / 4};
        int tot = j0.n4 + j1.n4 + j2.n4 + j3.n4 + j4.n4;
        split_all_kernel<<<(tot + 255) / 256, 256>>>(j0, j1, j2, j3, j4);
    }

    // QKV projections
    gemm_fp16x3<<<dim3(HIDDEN / 128, S_LEN / 128), 256, GEMM_SMEM_BYTES>>>(
        hsH, hsL, wqH, wqL, qraw, S_LEN, HIDDEN, HIDDEN);
    gemm_fp16x3<<<dim3(NKV * HD / 128, S_LEN / 128), 256, GEMM_SMEM_BYTES>>>(
        hsH, hsL, wkH, wkL, kraw, S_LEN, NKV * HD, HIDDEN);
    gemm_fp16x3<<<dim3(NKV * HD / 128, S_LEN / 128), 256, GEMM_SMEM_BYTES>>>(
        hsH, hsL, wvH, wvL, vraw, S_LEN, NKV * HD, HIDDEN);

    // RMSNorm (+RoPE), emit fp16 hi/lo (Q,K) and transposed fp16 (V)
    norm_rope_fp16<<<(S_LEN * NH + 3) / 4, 128>>>(qraw, qnH, qnL, qw, cosT, sinT, NH, 1);
    norm_rope_fp16<<<(S_LEN * NKV + 3) / 4, 128>>>(kraw, knH, knL, kw, cosT, sinT, NKV, 1);
    norm_rope_fp16<<<(S_LEN * NKV + 3) / 4, 128>>>(vraw, vnT, nullptr, nullptr, cosT, sinT, NKV, 0);

    // attention (head-major grid; rb reversed inside kernel for load balance)
    attn_fp16_kernel<<<dim3(NH, S_LEN / 128), 256, ATTN_SMEM_BYTES>>>(
        qnH, qnL, knH, knL, vnT, aoH, aoL);

    // output projection
    gemm_fp16x3<<<dim3(HIDDEN / 128, S_LEN / 128), 256, GEMM_SMEM_BYTES>>>(
        aoH, aoL, woH, woL, out, S_LEN, HIDDEN, HIDDEN);
}

// round 7
// speedup vs baseline: 4.4753x; 1.1920x over previous
#include <cuda_runtime.h>
#include <cuda_fp16.h>
#include <math.h>
#include <stdint.h>

#define S_LEN 4096
#define HIDDEN 2048
#define NH 16
#define NKV 4
#define HD 128

// ---------------- device-global scratch (no runtime alloc allowed) ----------
__device__ float g_Qraw[S_LEN * HIDDEN];
__device__ float g_Kraw[S_LEN * NKV * HD];
__device__ float g_Vraw[S_LEN * NKV * HD];

__device__ __half g_hsH[S_LEN * HIDDEN],   g_hsL[S_LEN * HIDDEN];
__device__ __half g_WqH[HIDDEN * HIDDEN],  g_WqL[HIDDEN * HIDDEN];
__device__ __half g_WkH[NKV * HD * HIDDEN], g_WkL[NKV * HD * HIDDEN];
__device__ __half g_WvH[NKV * HD * HIDDEN], g_WvL[NKV * HD * HIDDEN];
__device__ __half g_WoH[HIDDEN * HIDDEN],  g_WoL[HIDDEN * HIDDEN];

__device__ __half g_QnH[NH * S_LEN * HD],  g_QnL[NH * S_LEN * HD];   // [h][s][d]
__device__ __half g_KnH[NKV * S_LEN * HD], g_KnL[NKV * S_LEN * HD];  // [kv][s][d]
__device__ __half g_VnT[NKV * HD * S_LEN];                           // [kv][d][s]
__device__ __half g_AOH[S_LEN * HIDDEN],   g_AOL[S_LEN * HIDDEN];    // [s][hid]

// ---------------- helpers ---------------------------------------------------
__device__ __forceinline__ void split16(float x, __half& hi, __half& lo) {
    hi = __float2half_rn(x);
    lo = __float2half_rn(x - __half2float(hi));
}
__device__ __forceinline__ void cp16(uint32_t dst, const void* src) {
    asm volatile("cp.async.cg.shared.global [%0], [%1], 16;\n" :: "r"(dst), "l"(src));
}
__device__ __forceinline__ void cp_commit() {
    asm volatile("cp.async.commit_group;\n");
}
template <int N>
__device__ __forceinline__ void cp_wait() {
    asm volatile("cp.async.wait_group %0;\n" :: "n"(N));
}
__device__ __forceinline__ void ldsm4(uint32_t* r, uint32_t a) {
    asm volatile("ldmatrix.sync.aligned.m8n8.x4.shared.b16 {%0,%1,%2,%3}, [%4];\n"
                 : "=r"(r[0]), "=r"(r[1]), "=r"(r[2]), "=r"(r[3]) : "r"(a));
}
// fp16 m16n8k16, fp32 accum.
// A: a0=(g,k2t4..+1) a1=(g+8,same) a2=(g,k+8..) a3=(g+8,k+8..)
// B: b0=(k2t4..+1,n g) b1=(k+8..,n g);  C: c0,c1=(g,2t4,2t4+1) c2,c3=(g+8,..)
__device__ __forceinline__ void mma16(float* c, const uint32_t* a, const uint32_t* b) {
    asm volatile(
        "mma.sync.aligned.m16n8k16.row.col.f32.f16.f16.f32 "
        "{%0,%1,%2,%3},{%4,%5,%6,%7},{%8,%9},{%0,%1,%2,%3};\n"
        : "+f"(c[0]), "+f"(c[1]), "+f"(c[2]), "+f"(c[3])
        : "r"(a[0]), "r"(a[1]), "r"(a[2]), "r"(a[3]), "r"(b[0]), "r"(b[1]));
}
__device__ __forceinline__ uint32_t pack2(float a, float b) {
    __half2 t = __halves2half2(__float2half_rn(a), __float2half_rn(b));
    return *reinterpret_cast<uint32_t*>(&t);
}

// ---------------- fused fp32 -> fp16 hi/lo split (5 tensors, 1 launch) ------
struct SplitJob { const float* in; __half* hi; __half* lo; int n4; };

__global__ void __launch_bounds__(256) split_all_kernel(
    SplitJob j0, SplitJob j1, SplitJob j2, SplitJob j3, SplitJob j4)
{
    int i = blockIdx.x * 256 + threadIdx.x;
    const float* in; __half *hi, *lo;
    if (i < j0.n4)      { in = j0.in; hi = j0.hi; lo = j0.lo; }
    else if ((i -= j0.n4) < j1.n4) { in = j1.in; hi = j1.hi; lo = j1.lo; }
    else if ((i -= j1.n4) < j2.n4) { in = j2.in; hi = j2.hi; lo = j2.lo; }
    else if ((i -= j2.n4) < j3.n4) { in = j3.in; hi = j3.hi; lo = j3.lo; }
    else if ((i -= j3.n4) < j4.n4) { in = j4.in; hi = j4.hi; lo = j4.lo; }
    else return;
    float4 v = ((const float4*)in)[i];
    __half h0, l0, h1, l1, h2, l2, h3, l3;
    split16(v.x, h0, l0); split16(v.y, h1, l1);
    split16(v.z, h2, l2); split16(v.w, h3, l3);
    ((__half2*)hi)[2 * i]     = __halves2half2(h0, h1);
    ((__half2*)hi)[2 * i + 1] = __halves2half2(h2, h3);
    ((__half2*)lo)[2 * i]     = __halves2half2(l0, l1);
    ((__half2*)lo)[2 * i + 1] = __halves2half2(l2, l3);
}

// ---------------- fp16x3 GEMM core: C[128,128] tile of A@B^T ----------------
// 256 thr (8 warps, 32x64 warp tiles), k-chunk 32, 2-stage cp.async,
// ldmatrix frags. Designed for 2 CTAs/SM.
#define GK 32
#define GLDH 40                       // halves per smem row (32 + 8 pad)
#define GARR (128 * GLDH)             // halves per array per stage
#define GSTAGE (4 * GARR)             // Ah, Al, Bh, Bl
#define GEMM_SMEM_BYTES (2 * GSTAGE * 2)

__device__ __forceinline__ void gemm_core(
    const __half* __restrict__ A0h, const __half* __restrict__ A0l,
    const __half* __restrict__ B0h, const __half* __restrict__ B0l,
    float* __restrict__ Cb, int N, int K)
{
    extern __shared__ __half smh[];
    uint32_t sbase = (uint32_t)__cvta_generic_to_shared(smh);
    const int tid = threadIdx.x, w = tid >> 5, lane = tid & 31;
    const int g = lane >> 2, t4 = lane & 3;
    const int wm = w >> 1, wn = w & 1;
    const int la7 = lane & 7, lb = (lane >> 3) & 1, lc = (lane >> 4) & 1;
    const uint32_t offA = ((uint32_t)(wm * 32 + la7 + lb * 8) * GLDH + lc * 8) * 2;
    const uint32_t offB = ((uint32_t)(wn * 64 + lc * 8 + la7) * GLDH + lb * 8) * 2;
    const int nch = K / GK;

    float acc[2][8][4];
#pragma unroll
    for (int mt = 0; mt < 2; mt++)
#pragma unroll
        for (int nt = 0; nt < 8; nt++)
#pragma unroll
            for (int r = 0; r < 4; r++) acc[mt][nt][r] = 0.f;

    auto issue = [&](int chunk) {
        uint32_t sb = sbase + (uint32_t)((chunk & 1) * GSTAGE * 2);
        int k0 = chunk * GK;
#pragma unroll
        for (int j = 0; j < 2; j++) {
            int c = tid + j * 256;            // 0..511
            int row = c >> 2, seg = c & 3;    // 16B chunks
            size_t go = (size_t)row * K + k0 + seg * 8;
            uint32_t so = (uint32_t)(row * GLDH + seg * 8) * 2;
            cp16(sb + 0 * GARR * 2 + so, A0h + go);
            cp16(sb + 1 * GARR * 2 + so, A0l + go);
            cp16(sb + 2 * GARR * 2 + so, B0h + go);
            cp16(sb + 3 * GARR * 2 + so, B0l + go);
        }
    };

    issue(0); cp_commit();

    for (int i = 0; i < nch; i++) {
        if (i + 1 < nch) { issue(i + 1); cp_commit(); cp_wait<1>(); }
        else             { cp_wait<0>(); }
        __syncthreads();
        uint32_t base = sbase + (uint32_t)((i & 1) * GSTAGE * 2);
#pragma unroll
        for (int ks = 0; ks < 2; ks++) {
            uint32_t ah[2][4], al[2][4];
#pragma unroll
            for (int mt = 0; mt < 2; mt++) {
                uint32_t o = offA + (uint32_t)(mt * 16 * GLDH + ks * 16) * 2;
                ldsm4(ah[mt], base + o);
                ldsm4(al[mt], base + GARR * 2 + o);
            }
#pragma unroll
            for (int p = 0; p < 4; p++) {
                uint32_t bh4[4], bl4[4];
                uint32_t o = offB + (uint32_t)(p * 16 * GLDH + ks * 16) * 2;
                ldsm4(bh4, base + 2 * GARR * 2 + o);
                ldsm4(bl4, base + 3 * GARR * 2 + o);
#pragma unroll
                for (int q = 0; q < 2; q++) {
                    int nt = p * 2 + q;
                    uint32_t bh2[2] = {bh4[q * 2], bh4[q * 2 + 1]};
                    uint32_t bl2[2] = {bl4[q * 2], bl4[q * 2 + 1]};
                    mma16(acc[0][nt], ah[0], bh2);
                    mma16(acc[1][nt], ah[1], bh2);
                    mma16(acc[0][nt], ah[0], bl2);
                    mma16(acc[1][nt], ah[1], bl2);
                    mma16(acc[0][nt], al[0], bh2);
                    mma16(acc[1][nt], al[1], bh2);
                }
            }
        }
        __syncthreads();
    }

#pragma unroll
    for (int mt = 0; mt < 2; mt++) {
        int r0 = wm * 32 + mt * 16 + g;
#pragma unroll
        for (int nt = 0; nt < 8; nt++) {
            int col = wn * 64 + nt * 8 + 2 * t4;
            *(float2*)&Cb[(size_t)r0 * N + col] =
                make_float2(acc[mt][nt][0], acc[mt][nt][1]);
            *(float2*)&Cb[(size_t)(r0 + 8) * N + col] =
                make_float2(acc[mt][nt][2], acc[mt][nt][3]);
        }
    }
}

// fused QKV projection: bx 0..15 -> Q, 16..19 -> K, 20..23 -> V
__global__ void __launch_bounds__(256, 2) qkv_gemm_kernel(
    const __half* __restrict__ hsH, const __half* __restrict__ hsL,
    const __half* __restrict__ wqH, const __half* __restrict__ wqL,
    const __half* __restrict__ wkH, const __half* __restrict__ wkL,
    const __half* __restrict__ wvH, const __half* __restrict__ wvL,
    float* __restrict__ qraw, float* __restrict__ kraw, float* __restrict__ vraw)
{
    const int bx = blockIdx.x, by = blockIdx.y;
    const __half *Bh, *Bl; float* C; int N, cx;
    if (bx < 16)      { Bh = wqH; Bl = wqL; C = qraw; N = HIDDEN;   cx = bx; }
    else if (bx < 20) { Bh = wkH; Bl = wkL; C = kraw; N = NKV * HD; cx = bx - 16; }
    else              { Bh = wvH; Bl = wvL; C = vraw; N = NKV * HD; cx = bx - 20; }
    gemm_core(hsH + (size_t)by * 128 * HIDDEN, hsL + (size_t)by * 128 * HIDDEN,
              Bh + (size_t)cx * 128 * HIDDEN, Bl + (size_t)cx * 128 * HIDDEN,
              C + (size_t)by * 128 * N + cx * 128, N, HIDDEN);
}

// generic NT GEMM (output projection)
__global__ void __launch_bounds__(256, 2) gemm_fp16x3(
    const __half* __restrict__ Ah, const __half* __restrict__ Al,
    const __half* __restrict__ Bh, const __half* __restrict__ Bl,
    float* __restrict__ C, int M, int N, int K)
{
    gemm_core(Ah + (size_t)blockIdx.y * 128 * K, Al + (size_t)blockIdx.y * 128 * K,
              Bh + (size_t)blockIdx.x * 128 * K, Bl + (size_t)blockIdx.x * 128 * K,
              C + (size_t)blockIdx.y * 128 * N + blockIdx.x * 128, N, K);
}

// ---------------- fused RMSNorm (+RoPE) for Q, K, V -------------------------
__device__ __forceinline__ void norm_task_rope(
    const float* __restrict__ in, __half* __restrict__ outH,
    __half* __restrict__ outL, const float* __restrict__ w,
    const float* __restrict__ cosT, const float* __restrict__ sinT,
    int nheads, int task, int lane)
{
    int s = task / nheads, hh = task - s * nheads;
    const float* x = in + (size_t)s * (nheads * HD) + hh * HD;
    float v0 = x[lane], v1 = x[lane + 32], v2 = x[lane + 64], v3 = x[lane + 96];
    float ss = v0 * v0 + v1 * v1 + v2 * v2 + v3 * v3;
#pragma unroll
    for (int o = 16; o > 0; o >>= 1) ss += __shfl_xor_sync(0xFFFFFFFFu, ss, o);
    float inv = rsqrtf(ss * (1.f / HD) + 1e-6f);
    float n0 = v0 * inv * w[lane], n1 = v1 * inv * w[lane + 32];
    float n2 = v2 * inv * w[lane + 64], n3 = v3 * inv * w[lane + 96];
    const float* c  = cosT + (size_t)s * HD;
    const float* sn = sinT + (size_t)s * HD;
    float o0 = n0 * c[lane]      - n2 * sn[lane];
    float o1 = n1 * c[lane + 32] - n3 * sn[lane + 32];
    float o2 = n2 * c[lane + 64] + n0 * sn[lane + 64];
    float o3 = n3 * c[lane + 96] + n1 * sn[lane + 96];
    __half ah, al;
    __half* yh = outH + ((size_t)hh * S_LEN + s) * HD;
    __half* yl = outL + ((size_t)hh * S_LEN + s) * HD;
    split16(o0, ah, al); yh[lane] = ah;      yl[lane] = al;
    split16(o1, ah, al); yh[lane + 32] = ah; yl[lane + 32] = al;
    split16(o2, ah, al); yh[lane + 64] = ah; yl[lane + 64] = al;
    split16(o3, ah, al); yh[lane + 96] = ah; yl[lane + 96] = al;
}

__global__ void __launch_bounds__(128) norm_all_kernel(
    const float* __restrict__ qraw, const float* __restrict__ kraw,
    const float* __restrict__ vraw,
    __half* __restrict__ qnH, __half* __restrict__ qnL,
    __half* __restrict__ knH, __half* __restrict__ knL,
    __half* __restrict__ vnT,
    const float* __restrict__ qw, const float* __restrict__ kw,
    const float* __restrict__ cosT, const float* __restrict__ sinT)
{
    int t = blockIdx.x * 4 + (threadIdx.x >> 5);
    int lane = threadIdx.x & 31;
    const int NQ = S_LEN * NH, NK = S_LEN * NKV;
    if (t < NQ) {
        norm_task_rope(qraw, qnH, qnL, qw, cosT, sinT, NH, t, lane);
    } else if ((t -= NQ) < NK) {
        norm_task_rope(kraw, knH, knL, kw, cosT, sinT, NKV, t, lane);
    } else if ((t -= NK) < NK) {
        int s = t / NKV, hh = t - s * NKV;
        const float* x = vraw + (size_t)s * (NKV * HD) + hh * HD;
        float v0 = x[lane], v1 = x[lane + 32], v2 = x[lane + 64], v3 = x[lane + 96];
        float ss = v0 * v0 + v1 * v1 + v2 * v2 + v3 * v3;
#pragma unroll
        for (int o = 16; o > 0; o >>= 1) ss += __shfl_xor_sync(0xFFFFFFFFu, ss, o);
        float inv = rsqrtf(ss * (1.f / HD) + 1e-6f);
        __half* y = vnT + (size_t)hh * HD * S_LEN;
        y[(size_t)(lane)      * S_LEN + s] = __float2half_rn(v0 * inv);
        y[(size_t)(lane + 32) * S_LEN + s] = __float2half_rn(v1 * inv);
        y[(size_t)(lane + 64) * S_LEN + s] = __float2half_rn(v2 * inv);
        y[(size_t)(lane + 96) * S_LEN + s] = __float2half_rn(v3 * inv);
    }
}

// ---------------- causal GQA flash attention, fp16 MMA ----------------------
// Block: 128 q-rows x head. 256 thr = 8 warps; warp w owns rows 16w..16w+15
// and ALL 64 key cols -> softmax fully warp-local, P stays in registers.
// QK^T fp16x3, PV single fp16; cp.async double-buffered K/V; 1 barrier/tile.
#define ALDQ 136
#define ALDV 72
#define OFF_QH 0
#define OFF_QL (128 * ALDQ)
#define OFF_KH0 (2 * 128 * ALDQ)
#define OFF_KL0 (OFF_KH0 + 64 * ALDQ)
#define OFF_KH1 (OFF_KL0 + 64 * ALDQ)
#define OFF_KL1 (OFF_KH1 + 64 * ALDQ)
#define OFF_VT0 (OFF_KL1 + 64 * ALDQ)
#define OFF_VT1 (OFF_VT0 + 128 * ALDV)
#define HALVES_TOT (OFF_VT1 + 128 * ALDV)
#define ATTN_SMEM_BYTES (HALVES_TOT * 2)

__global__ void __launch_bounds__(256) attn_fp16_kernel(
    const __half* __restrict__ Qh_g, const __half* __restrict__ Ql_g,
    const __half* __restrict__ Kh_g, const __half* __restrict__ Kl_g,
    const __half* __restrict__ Vt_g,
    __half* __restrict__ AOh, __half* __restrict__ AOl)
{
    extern __shared__ __half sm[];
    __half* Qh = sm + OFF_QH;
    __half* Ql = sm + OFF_QL;
    uint32_t su = (uint32_t)__cvta_generic_to_shared(sm);
    const uint32_t uKH[2] = {su + OFF_KH0 * 2, su + OFF_KH1 * 2};
    const uint32_t uKL[2] = {su + OFF_KL0 * 2, su + OFF_KL1 * 2};
    const uint32_t uVT[2] = {su + OFF_VT0 * 2, su + OFF_VT1 * 2};

    const int hq = blockIdx.x;
    const int rb = (gridDim.y - 1) - blockIdx.y;   // heavy blocks first
    const int kvh = hq >> 2;
    const int tid = threadIdx.x, w = tid >> 5, lane = tid & 31;
    const int g = lane >> 2, t4 = lane & 3;
    const int m0 = 16 * w;
    const int la7 = lane & 7, lb = (lane >> 3) & 1, lc = (lane >> 4) & 1;

    const uint32_t offQA = ((uint32_t)(m0 + la7 + lb * 8) * ALDQ + lc * 8) * 2;
    const uint32_t offKB = ((uint32_t)(lc * 8 + la7) * ALDQ + lb * 8) * 2;
    const uint32_t offVB = ((uint32_t)(lc * 8 + la7) * ALDV + lb * 8) * 2;

    const __half* Qg_h = Qh_g + ((size_t)hq * S_LEN + rb * 128) * HD;
    const __half* Qg_l = Ql_g + ((size_t)hq * S_LEN + rb * 128) * HD;
    const __half* Kg_h = Kh_g + (size_t)kvh * S_LEN * HD;
    const __half* Kg_l = Kl_g + (size_t)kvh * S_LEN * HD;
    const __half* Vg   = Vt_g + (size_t)kvh * HD * S_LEN;

    auto issueKV = [&](int kb) {
        int st = kb & 1;
#pragma unroll
        for (int j = 0; j < 4; j++) {
            int c = tid + j * 256;            // 0..1023
            int row = c >> 4, seg = c & 15;
            size_t go = (size_t)(kb * 64 + row) * HD + seg * 8;
            uint32_t so = (uint32_t)(row * ALDQ + seg * 8) * 2;
            cp16(uKH[st] + so, Kg_h + go);
            cp16(uKL[st] + so, Kg_l + go);
            int vrow = c >> 3, vseg = c & 7;
            cp16(uVT[st] + (uint32_t)(vrow * ALDV + vseg * 8) * 2,
                 Vg + (size_t)vrow * S_LEN + kb * 64 + vseg * 8);
        }
    };

    issueKV(0); cp_commit();

    // Q tiles hi/lo (plain loads, overlap with cp.async)
#pragma unroll
    for (int j = 0; j < 8; j++) {
        int c = tid + j * 256;
        int row = c >> 4, seg = c & 15;
        *(uint4*)&Qh[row * ALDQ + seg * 8] =
            *(const uint4*)(Qg_h + (size_t)row * HD + seg * 8);
        *(uint4*)&Ql[row * ALDQ + seg * 8] =
            *(const uint4*)(Qg_l + (size_t)row * HD + seg * 8);
    }

    float mL = -INFINITY, mH = -INFINITY, lLs = 0.f, lHs = 0.f;
    float oacc[16][4];
#pragma unroll
    for (int nt = 0; nt < 16; nt++)
#pragma unroll
        for (int r = 0; r < 4; r++) oacc[nt][r] = 0.f;

    const int kbmax = 2 * rb + 1;
    for (int kb = 0; kb <= kbmax; kb++) {
        const int st = kb & 1;
        cp_wait<0>();
        __syncthreads();   // tile kb resident; all warps done reading st^1
        if (kb + 1 <= kbmax) { issueKV(kb + 1); cp_commit(); }

        // warps whose rows are entirely above the diagonal tile: skip
        if (kb == kbmax && m0 + 15 < 64) continue;

        // ---- S = Q K^T (fp16x3): 16 rows x 64 cols per warp ----
        float sacc[8][4];
#pragma unroll
        for (int nt = 0; nt < 8; nt++)
#pragma unroll
            for (int r = 0; r < 4; r++) sacc[nt][r] = 0.f;

#pragma unroll
        for (int ks = 0; ks < 8; ks++) {
            uint32_t ah[4], al[4];
            uint32_t oq = offQA + (uint32_t)(ks * 16) * 2;
            ldsm4(ah, su + OFF_QH * 2 + oq);
            ldsm4(al, su + OFF_QL * 2 + oq);
#pragma unroll
            for (int p = 0; p < 4; p++) {
                uint32_t bh4[4], bl4[4];
                uint32_t o = offKB + (uint32_t)(p * 16 * ALDQ + ks * 16) * 2;
                ldsm4(bh4, uKH[st] + o);
                ldsm4(bl4, uKL[st] + o);
#pragma unroll
                for (int q = 0; q < 2; q++) {
                    int nt = p * 2 + q;
                    uint32_t bh2[2] = {bh4[q * 2], bh4[q * 2 + 1]};
                    uint32_t bl2[2] = {bl4[q * 2], bl4[q * 2 + 1]};
                    mma16(sacc[nt], ah, bh2);
                    mma16(sacc[nt], ah, bl2);
                    mma16(sacc[nt], al, bh2);
                }
            }
        }

        // ---- causal mask ----
        if (kb >= 2 * rb) {
            int r0 = rb * 128 + m0 + g, r1 = r0 + 8;
#pragma unroll
            for (int nt = 0; nt < 8; nt++) {
                int c0 = kb * 64 + nt * 8 + 2 * t4;
                if (c0 > r0)     sacc[nt][0] = -INFINITY;
                if (c0 + 1 > r0) sacc[nt][1] = -INFINITY;
                if (c0 > r1)     sacc[nt][2] = -INFINITY;
                if (c0 + 1 > r1) sacc[nt][3] = -INFINITY;
            }
        }

        // ---- warp-local online softmax ----
        float rmL = -INFINITY, rmH = -INFINITY;
#pragma unroll
        for (int nt = 0; nt < 8; nt++) {
            rmL = fmaxf(rmL, fmaxf(sacc[nt][0], sacc[nt][1]));
            rmH = fmaxf(rmH, fmaxf(sacc[nt][2], sacc[nt][3]));
        }
        rmL = fmaxf(rmL, __shfl_xor_sync(0xFFFFFFFFu, rmL, 1));
        rmL = fmaxf(rmL, __shfl_xor_sync(0xFFFFFFFFu, rmL, 2));
        rmH = fmaxf(rmH, __shfl_xor_sync(0xFFFFFFFFu, rmH, 1));
        rmH = fmaxf(rmH, __shfl_xor_sync(0xFFFFFFFFu, rmH, 2));
        float mnL = fmaxf(mL, rmL), mnH = fmaxf(mH, rmH);
        float aL = __expf(mL - mnL), aH = __expf(mH - mnH);
        mL = mnL; mH = mnH;

        uint32_t pfL[8], pfH[8];
        float lsL = 0.f, lsH = 0.f;
#pragma unroll
        for (int nt = 0; nt < 8; nt++) {
            float p0 = __expf(sacc[nt][0] - mnL);
            float p1 = __expf(sacc[nt][1] - mnL);
            float p2 = __expf(sacc[nt][2] - mnH);
            float p3 = __expf(sacc[nt][3] - mnH);
            lsL += p0 + p1; lsH += p2 + p3;
            pfL[nt] = pack2(p0, p1);
            pfH[nt] = pack2(p2, p3);
        }
        lsL += __shfl_xor_sync(0xFFFFFFFFu, lsL, 1);
        lsL += __shfl_xor_sync(0xFFFFFFFFu, lsL, 2);
        lsH += __shfl_xor_sync(0xFFFFFFFFu, lsH, 1);
        lsH += __shfl_xor_sync(0xFFFFFFFFu, lsH, 2);
        lLs = lLs * aL + lsL;
        lHs = lHs * aH + lsH;

#pragma unroll
        for (int nt = 0; nt < 16; nt++) {
            oacc[nt][0] *= aL; oacc[nt][1] *= aL;
            oacc[nt][2] *= aH; oacc[nt][3] *= aH;
        }

        // ---- O += P @ V (P fragments straight from registers) ----
#pragma unroll
        for (int ks = 0; ks < 4; ks++) {
            uint32_t pa[4] = {pfL[2 * ks], pfH[2 * ks], pfL[2 * ks + 1], pfH[2 * ks + 1]};
#pragma unroll
            for (int p = 0; p < 8; p++) {
                uint32_t vb4[4];
                uint32_t o = offVB + (uint32_t)(p * 16 * ALDV + ks * 16) * 2;
                ldsm4(vb4, uVT[st] + o);
                uint32_t b0[2] = {vb4[0], vb4[1]};
                uint32_t b1[2] = {vb4[2], vb4[3]};
                mma16(oacc[2 * p],     pa, b0);
                mma16(oacc[2 * p + 1], pa, b1);
            }
        }
    }

    // ---- epilogue: normalize, split fp16 hi/lo, store AO [s][hid] ----
    float invL = 1.f / lLs, invH = 1.f / lHs;
    size_t sL = (size_t)(rb * 128 + m0 + g) * HIDDEN;
    size_t sH = (size_t)(rb * 128 + m0 + g + 8) * HIDDEN;
#pragma unroll
    for (int nt = 0; nt < 16; nt++) {
        int col = hq * HD + nt * 8 + 2 * t4;
        __half h0, l0, h1, l1;
        split16(oacc[nt][0] * invL, h0, l0);
        split16(oacc[nt][1] * invL, h1, l1);
        *(__half2*)&AOh[sL + col] = __halves2half2(h0, h1);
        *(__half2*)&AOl[sL + col] = __halves2half2(l0, l1);
        split16(oacc[nt][2] * invH, h0, l0);
        split16(oacc[nt][3] * invH, h1, l1);
        *(__half2*)&AOh[sH + col] = __halves2half2(h0, h1);
        *(__half2*)&AOl[sH + col] = __halves2half2(l0, l1);
    }
}

// ---------------------------------------------------------------------------
extern "C" void kernel_launch(void* const* d_in, const int* in_sizes, int n_in,
                              void* d_out, int out_size)
{
    const float* hs   = (const float*)d_in[0];
    const float* cosT = (const float*)d_in[1];
    const float* sinT = (const float*)d_in[2];
    // d_in[3] = attention_mask: pure causal, implemented directly (not read)
    const float* Wq = (const float*)d_in[4];
    const float* Wk = (const float*)d_in[5];
    const float* Wv = (const float*)d_in[6];
    const float* Wo = (const float*)d_in[7];
    const float* qw = (const float*)d_in[8];
    const float* kw = (const float*)d_in[9];
    float* out = (float*)d_out;

    float *qraw, *kraw, *vraw;
    __half *hsH, *hsL, *wqH, *wqL, *wkH, *wkL, *wvH, *wvL, *woH, *woL;
    __half *qnH, *qnL, *knH, *knL, *vnT, *aoH, *aoL;
    cudaGetSymbolAddress((void**)&qraw, g_Qraw);
    cudaGetSymbolAddress((void**)&kraw, g_Kraw);
    cudaGetSymbolAddress((void**)&vraw, g_Vraw);
    cudaGetSymbolAddress((void**)&hsH, g_hsH); cudaGetSymbolAddress((void**)&hsL, g_hsL);
    cudaGetSymbolAddress((void**)&wqH, g_WqH); cudaGetSymbolAddress((void**)&wqL, g_WqL);
    cudaGetSymbolAddress((void**)&wkH, g_WkH); cudaGetSymbolAddress((void**)&wkL, g_WkL);
    cudaGetSymbolAddress((void**)&wvH, g_WvH); cudaGetSymbolAddress((void**)&wvL, g_WvL);
    cudaGetSymbolAddress((void**)&woH, g_WoH); cudaGetSymbolAddress((void**)&woL, g_WoL);
    cudaGetSymbolAddress((void**)&qnH, g_QnH); cudaGetSymbolAddress((void**)&qnL, g_QnL);
    cudaGetSymbolAddress((void**)&knH, g_KnH); cudaGetSymbolAddress((void**)&knL, g_KnL);
    cudaGetSymbolAddress((void**)&vnT, g_VnT);
    cudaGetSymbolAddress((void**)&aoH, g_AOH); cudaGetSymbolAddress((void**)&aoL, g_AOL);

    cudaFuncSetAttribute(qkv_gemm_kernel,
                         cudaFuncAttributeMaxDynamicSharedMemorySize, GEMM_SMEM_BYTES);
    cudaFuncSetAttribute(gemm_fp16x3,
                         cudaFuncAttributeMaxDynamicSharedMemorySize, GEMM_SMEM_BYTES);
    cudaFuncSetAttribute(attn_fp16_kernel,
                         cudaFuncAttributeMaxDynamicSharedMemorySize, ATTN_SMEM_BYTES);

    // split inputs to fp16 hi/lo (single fused launch)
    {
        SplitJob j0 = {hs, hsH, hsL, S_LEN * HIDDEN / 4};
        SplitJob j1 = {Wq, wqH, wqL, HIDDEN * HIDDEN / 4};
        SplitJob j2 = {Wk, wkH, wkL, NKV * HD * HIDDEN / 4};
        SplitJob j3 = {Wv, wvH, wvL, NKV * HD * HIDDEN / 4};
        SplitJob j4 = {Wo, woH, woL, HIDDEN * HIDDEN / 4};
        int tot = j0.n4 + j1.n4 + j2.n4 + j3.n4 + j4.n4;
        split_all_kernel<<<(tot + 255) / 256, 256>>>(j0, j1, j2, j3, j4);
    }

    // fused QKV projections
    qkv_gemm_kernel<<<dim3(24, S_LEN / 128), 256, GEMM_SMEM_BYTES>>>(
        hsH, hsL, wqH, wqL, wkH, wkL, wvH, wvL, qraw, kraw, vraw);

    // fused RMSNorm (+RoPE) for Q, K, V
    {
        int tasks = S_LEN * (NH + NKV + NKV);
        norm_all_kernel<<<(tasks + 3) / 4, 128>>>(
            qraw, kraw, vraw, qnH, qnL, knH, knL, vnT, qw, kw, cosT, sinT);
    }

    // attention (head-major grid; rb reversed inside kernel)
    attn_fp16_kernel<<<dim3(NH, S_LEN / 128), 256, ATTN_SMEM_BYTES>>>(
        qnH, qnL, knH, knL, vnT, aoH, aoL);

    // output projection
    gemm_fp16x3<<<dim3(HIDDEN / 128, S_LEN / 128), 256, GEMM_SMEM_BYTES>>>(
        aoH, aoL, woH, woL, out, S_LEN, HIDDEN, HIDDEN);
}